// round 5
// baseline (speedup 1.0000x reference)
#include <cuda_runtime.h>
#include <cstddef>
#include <cstdint>

// ---------------- problem constants ----------------
#define KVOCAB 100000
#define KED    200
#define KH     100      // HW == HS == 100
#define KNC    10
#define KB     128
#define KS     40
#define KW     50
#define KSENT  (KB * KS)          // 5120

// ---------------- scratch (__device__ globals; no allocations allowed) ----
__device__ float g_gates[(size_t)KVOCAB * 600];   // 240 MB, reused as U buffer & sentence gates
__device__ float g_wenc[(size_t)KVOCAB * 200];    // 80 MB: per-vocab word encoding table
__device__ float g_scorew[KVOCAB];                // per-vocab word attention score
__device__ float g_svec[KSENT * 200];
__device__ float g_senc[KSENT * 200];
__device__ float g_scores[KSENT];
__device__ float g_dvec[KB * 200];
__device__ float g_WcatW[600 * KED];              // [w_Wih_f ; w_Wih_b]
__device__ float g_bihW[600];
__device__ float g_WcatS[600 * 200];              // [s_Wih_f ; s_Wih_b]
__device__ float g_bihS[600];

// ---------------- f32x2 helpers (FFMA2: ptxas never emits this from C++) ---
__device__ __forceinline__ unsigned long long pack2(float lo, float hi) {
    unsigned long long r;
    asm("mov.b64 %0, {%1, %2};" : "=l"(r) : "f"(lo), "f"(hi));
    return r;
}
__device__ __forceinline__ void unpack2(unsigned long long v, float& lo, float& hi) {
    asm("mov.b64 {%0, %1}, %2;" : "=f"(lo), "=f"(hi) : "l"(v));
}
__device__ __forceinline__ void ffma2(unsigned long long& d, unsigned long long a, unsigned long long b) {
    asm("fma.rn.f32x2 %0, %1, %2, %0;" : "+l"(d) : "l"(a), "l"(b));
}
__device__ __forceinline__ float fast_tanh(float x) {
    float y; asm("tanh.approx.f32 %0, %1;" : "=f"(y) : "f"(x)); return y;
}
__device__ __forceinline__ float sigmf(float x) {
    return 0.5f * fast_tanh(0.5f * x) + 0.5f;
}

// ---------------- SGEMM (NT): C[M,N] = A[M,K] * B[N,K]^T + bias[n] --------
// A row-major lda=K, B row-major ldb=K (both K-contiguous), C row-major ldc.
// Requires K % 8 == 0 (K is always 200 here). 128x128x8 tile, double-buffered,
// 256 threads, 8x8 per-thread tile, inner product in packed f32x2 FMAs.
__global__ __launch_bounds__(256)
void sgemm_nt(const float* __restrict__ A, const float* __restrict__ Bm,
              const float* __restrict__ bias, float* __restrict__ C,
              int M, int N, int K, int ldc)
{
    const int BM = 128, BN = 128, BK = 8, TM = 8, TN = 8;
    __shared__ float As[2][BK][BM];
    __shared__ float Bs[2][BK][BN];

    const int tid   = threadIdx.x;
    const int mBase = blockIdx.y * BM;
    const int nBase = blockIdx.x * BN;
    const int lrow  = tid >> 1;          // 0..127
    const int lcol  = (tid & 1) << 2;    // 0 or 4
    const int tx    = tid & 15;
    const int ty    = tid >> 4;
    const int tm0   = ty * TM;
    const int tn0   = tx * TN;

    unsigned long long acc[TM / 2][TN];
#pragma unroll
    for (int i = 0; i < TM / 2; i++)
#pragma unroll
        for (int j = 0; j < TN; j++) acc[i][j] = 0ull;

    const int nk = K >> 3;

    // prologue: stage tile 0
    {
        float4 va = make_float4(0.f, 0.f, 0.f, 0.f);
        float4 vb = make_float4(0.f, 0.f, 0.f, 0.f);
        int m = mBase + lrow;
        if (m < M) va = *reinterpret_cast<const float4*>(A + (size_t)m * K + lcol);
        int n = nBase + lrow;
        if (n < N) vb = *reinterpret_cast<const float4*>(Bm + (size_t)n * K + lcol);
        As[0][lcol + 0][lrow] = va.x; As[0][lcol + 1][lrow] = va.y;
        As[0][lcol + 2][lrow] = va.z; As[0][lcol + 3][lrow] = va.w;
        Bs[0][lcol + 0][lrow] = vb.x; Bs[0][lcol + 1][lrow] = vb.y;
        Bs[0][lcol + 2][lrow] = vb.z; Bs[0][lcol + 3][lrow] = vb.w;
    }
    __syncthreads();

    for (int kt = 0; kt < nk; kt++) {
        const int cur = kt & 1;
        float4 va = make_float4(0.f, 0.f, 0.f, 0.f);
        float4 vb = make_float4(0.f, 0.f, 0.f, 0.f);
        const bool hasNext = (kt + 1 < nk);
        if (hasNext) {
            int k = (kt + 1) * BK + lcol;
            int m = mBase + lrow;
            if (m < M) va = *reinterpret_cast<const float4*>(A + (size_t)m * K + k);
            int n = nBase + lrow;
            if (n < N) vb = *reinterpret_cast<const float4*>(Bm + (size_t)n * K + k);
        }
#pragma unroll
        for (int kk = 0; kk < BK; kk++) {
            float af[TM], bf[TN];
#pragma unroll
            for (int i = 0; i < TM; i++) af[i] = As[cur][kk][tm0 + i];
#pragma unroll
            for (int j = 0; j < TN; j++) bf[j] = Bs[cur][kk][tn0 + j];
            unsigned long long a2[TM / 2], b2[TN];
#pragma unroll
            for (int i = 0; i < TM / 2; i++) a2[i] = pack2(af[2 * i], af[2 * i + 1]);
#pragma unroll
            for (int j = 0; j < TN; j++) b2[j] = pack2(bf[j], bf[j]);
#pragma unroll
            for (int i = 0; i < TM / 2; i++)
#pragma unroll
                for (int j = 0; j < TN; j++) ffma2(acc[i][j], a2[i], b2[j]);
        }
        if (hasNext) {
            const int nxt = cur ^ 1;
            As[nxt][lcol + 0][lrow] = va.x; As[nxt][lcol + 1][lrow] = va.y;
            As[nxt][lcol + 2][lrow] = va.z; As[nxt][lcol + 3][lrow] = va.w;
            Bs[nxt][lcol + 0][lrow] = vb.x; Bs[nxt][lcol + 1][lrow] = vb.y;
            Bs[nxt][lcol + 2][lrow] = vb.z; Bs[nxt][lcol + 3][lrow] = vb.w;
            __syncthreads();
        }
    }

    // epilogue: unpack pairs (rows tm0+2i, tm0+2i+1), add bias, guarded store
#pragma unroll
    for (int i = 0; i < TM / 2; i++) {
#pragma unroll
        for (int j = 0; j < TN; j++) {
            float lo, hi;
            unpack2(acc[i][j], lo, hi);
            int n = nBase + tn0 + j;
            if (n < N) {
                float bv = bias[n];
                int m0 = mBase + tm0 + 2 * i;
                if (m0 < M)     C[(size_t)m0 * ldc + n]       = lo + bv;
                if (m0 + 1 < M) C[(size_t)(m0 + 1) * ldc + n] = hi + bv;
            }
        }
    }
}

// ---------------- GRU-from-zero pointwise -------------------------------
// gates layout per row (ldc=600): [r_f z_f n_f | r_b z_b n_b] (100 each),
// bih already added by the GEMM. h[m] = concat(h_f, h_b) (200).
__global__ void gru_pointwise(const float* __restrict__ g,
                              const float* __restrict__ bhh_f,
                              const float* __restrict__ bhh_b,
                              float* __restrict__ h, int M)
{
    int i = blockIdx.x * blockDim.x + threadIdx.x;
    if (i >= M * KH) return;
    int m = i / KH;
    int d = i - m * KH;
    const float* gr = g + (size_t)m * 600;
    float rf = sigmf(gr[d]       + bhh_f[d]);
    float zf = sigmf(gr[100 + d] + bhh_f[100 + d]);
    float nf = fast_tanh(gr[200 + d] + rf * bhh_f[200 + d]);
    float rb = sigmf(gr[300 + d] + bhh_b[d]);
    float zb = sigmf(gr[400 + d] + bhh_b[100 + d]);
    float nb = fast_tanh(gr[500 + d] + rb * bhh_b[200 + d]);
    float* hr = h + (size_t)m * 200;
    hr[d]       = (1.0f - zf) * nf;
    hr[100 + d] = (1.0f - zb) * nb;
}

// ---------------- score[m] = sum_d ctx[d] * tanh(U[m,d]) (U has bias) ----
__global__ void tanh_dot(const float* __restrict__ U, const float* __restrict__ ctx,
                         float* __restrict__ score, int M)
{
    int warp = (int)((blockIdx.x * blockDim.x + threadIdx.x) >> 5);
    int lane = threadIdx.x & 31;
    if (warp >= M) return;
    const float* u = U + (size_t)warp * 200;
    float s = 0.f;
    for (int d = lane; d < 200; d += 32) s += ctx[d] * fast_tanh(u[d]);
#pragma unroll
    for (int o = 16; o; o >>= 1) s += __shfl_xor_sync(0xffffffffu, s, o);
    if (lane == 0) score[warp] = s;
}

// ---------------- word attention combine: one block per sentence ---------
__global__ void word_attn(const int* __restrict__ x, const float* __restrict__ scoretab,
                          const float* __restrict__ wenc, float* __restrict__ svec)
{
    int s = blockIdx.x;                 // 0..KSENT-1
    __shared__ int   ids[KW];
    __shared__ float al[KW];
    __shared__ float sinv;
    int t = threadIdx.x;                // 256 threads
    if (t < KW) {
        int id = x[s * KW + t];
        ids[t] = id;
        al[t]  = scoretab[id];
    }
    __syncthreads();
    if (t == 0) {
        float mx = -1e30f;
        for (int w = 0; w < KW; w++) mx = fmaxf(mx, al[w]);
        float sum = 0.f;
        for (int w = 0; w < KW; w++) { float e = __expf(al[w] - mx); al[w] = e; sum += e; }
        sinv = 1.0f / sum;
    }
    __syncthreads();
    if (t < 200) {
        float acc = 0.f;
        float inv = sinv;
#pragma unroll 5
        for (int w = 0; w < KW; w++) acc += al[w] * wenc[(size_t)ids[w] * 200 + t];
        svec[(size_t)s * 200 + t] = acc * inv;
    }
}

// ---------------- sentence attention combine: one block per batch row ----
__global__ void sent_attn(const float* __restrict__ scoretab, const float* __restrict__ senc,
                          float* __restrict__ dvec)
{
    int b = blockIdx.x;
    __shared__ float al[KS];
    __shared__ float sinv;
    int t = threadIdx.x;
    if (t < KS) al[t] = scoretab[b * KS + t];
    __syncthreads();
    if (t == 0) {
        float mx = -1e30f;
        for (int i = 0; i < KS; i++) mx = fmaxf(mx, al[i]);
        float sum = 0.f;
        for (int i = 0; i < KS; i++) { float e = __expf(al[i] - mx); al[i] = e; sum += e; }
        sinv = 1.0f / sum;
    }
    __syncthreads();
    if (t < 200) {
        float acc = 0.f;
        float inv = sinv;
#pragma unroll 4
        for (int i = 0; i < KS; i++) acc += al[i] * senc[(size_t)(b * KS + i) * 200 + t];
        dvec[b * 200 + t] = acc * inv;
    }
}

// ---------------- classifier + log_softmax: one warp per batch row -------
__global__ void classifier(const float* __restrict__ dvec, const float* __restrict__ fcW,
                           const float* __restrict__ fcb, float* __restrict__ out)
{
    int b = blockIdx.x;
    int lane = threadIdx.x;             // 32 threads
    const float* dv = dvec + b * 200;
    float logit[KNC];
#pragma unroll
    for (int c = 0; c < KNC; c++) {
        float s = 0.f;
        for (int d = lane; d < 200; d += 32) s += dv[d] * fcW[c * 200 + d];
#pragma unroll
        for (int o = 16; o; o >>= 1) s += __shfl_xor_sync(0xffffffffu, s, o);
        logit[c] = s + fcb[c];          // xor-reduce -> all lanes hold the sum
    }
    if (lane == 0) {
        float mx = -1e30f;
        for (int c = 0; c < KNC; c++) mx = fmaxf(mx, logit[c]);
        float sum = 0.f;
        for (int c = 0; c < KNC; c++) sum += expf(logit[c] - mx);
        float lse = mx + logf(sum);
        for (int c = 0; c < KNC; c++) out[b * KNC + c] = logit[c] - lse;
    }
}

// ---------------- launch --------------------------------------------------
extern "C" void kernel_launch(void* const* d_in, const int* in_sizes, int n_in,
                              void* d_out, int out_size)
{
    (void)in_sizes; (void)n_in; (void)out_size;
    const int*   x     = (const int*)  d_in[0];
    const float* emb   = (const float*)d_in[1];
    const float* wWihf = (const float*)d_in[2];
    const float* wbihf = (const float*)d_in[3];
    const float* wbhhf = (const float*)d_in[4];
    const float* wWihb = (const float*)d_in[5];
    const float* wbihb = (const float*)d_in[6];
    const float* wbhhb = (const float*)d_in[7];
    const float* waW   = (const float*)d_in[8];
    const float* wab   = (const float*)d_in[9];
    const float* wactx = (const float*)d_in[10];
    const float* sWihf = (const float*)d_in[11];
    const float* sbihf = (const float*)d_in[12];
    const float* sbhhf = (const float*)d_in[13];
    const float* sWihb = (const float*)d_in[14];
    const float* sbihb = (const float*)d_in[15];
    const float* sbhhb = (const float*)d_in[16];
    const float* saW   = (const float*)d_in[17];
    const float* sab   = (const float*)d_in[18];
    const float* sactx = (const float*)d_in[19];
    const float* fcW   = (const float*)d_in[20];
    const float* fcb   = (const float*)d_in[21];
    float* out = (float*)d_out;

    float *gates, *wenc, *scorew, *svec, *senc, *scores, *dvec;
    float *WcatW, *bihW, *WcatS, *bihS;
    cudaGetSymbolAddress((void**)&gates,  g_gates);
    cudaGetSymbolAddress((void**)&wenc,   g_wenc);
    cudaGetSymbolAddress((void**)&scorew, g_scorew);
    cudaGetSymbolAddress((void**)&svec,   g_svec);
    cudaGetSymbolAddress((void**)&senc,   g_senc);
    cudaGetSymbolAddress((void**)&scores, g_scores);
    cudaGetSymbolAddress((void**)&dvec,   g_dvec);
    cudaGetSymbolAddress((void**)&WcatW,  g_WcatW);
    cudaGetSymbolAddress((void**)&bihW,   g_bihW);
    cudaGetSymbolAddress((void**)&WcatS,  g_WcatS);
    cudaGetSymbolAddress((void**)&bihS,   g_bihS);

    // concat fwd/bwd input weights & biases (capture-safe D2D copies)
    cudaMemcpyAsync(WcatW,            wWihf, (size_t)300 * KED * sizeof(float), cudaMemcpyDeviceToDevice, 0);
    cudaMemcpyAsync(WcatW + 300 * KED, wWihb, (size_t)300 * KED * sizeof(float), cudaMemcpyDeviceToDevice, 0);
    cudaMemcpyAsync(bihW,       wbihf, 300 * sizeof(float), cudaMemcpyDeviceToDevice, 0);
    cudaMemcpyAsync(bihW + 300, wbihb, 300 * sizeof(float), cudaMemcpyDeviceToDevice, 0);
    cudaMemcpyAsync(WcatS,            sWihf, (size_t)300 * 200 * sizeof(float), cudaMemcpyDeviceToDevice, 0);
    cudaMemcpyAsync(WcatS + 300 * 200, sWihb, (size_t)300 * 200 * sizeof(float), cudaMemcpyDeviceToDevice, 0);
    cudaMemcpyAsync(bihS,       sbihf, 300 * sizeof(float), cudaMemcpyDeviceToDevice, 0);
    cudaMemcpyAsync(bihS + 300, sbihb, 300 * sizeof(float), cudaMemcpyDeviceToDevice, 0);

    // --- word stage (per-vocab tables; tokens only gather) ---
    {   // gates = emb @ WcatW^T + bihW          [VOCAB, 600]
        dim3 grid((600 + 127) / 128, (KVOCAB + 127) / 128);
        sgemm_nt<<<grid, 256>>>(emb, WcatW, bihW, gates, KVOCAB, 600, KED, 600);
    }
    gru_pointwise<<<(KVOCAB * KH + 255) / 256, 256>>>(gates, wbhhf, wbhhb, wenc, KVOCAB);
    {   // U = wenc @ waW^T + wab (reuse gates buffer)   [VOCAB, 200]
        dim3 grid((200 + 127) / 128, (KVOCAB + 127) / 128);
        sgemm_nt<<<grid, 256>>>(wenc, waW, wab, gates, KVOCAB, 200, 200, 200);
    }
    tanh_dot<<<(KVOCAB + 7) / 8, 256>>>(gates, wactx, scorew, KVOCAB);
    word_attn<<<KSENT, 256>>>(x, scorew, wenc, svec);

    // --- sentence stage ---
    {   // gates_s = svec @ WcatS^T + bihS       [5120, 600]
        dim3 grid((600 + 127) / 128, (KSENT + 127) / 128);
        sgemm_nt<<<grid, 256>>>(svec, WcatS, bihS, gates, KSENT, 600, 200, 600);
    }
    gru_pointwise<<<(KSENT * KH + 255) / 256, 256>>>(gates, sbhhf, sbhhb, senc, KSENT);
    {   // U_s = senc @ saW^T + sab              [5120, 200]
        dim3 grid((200 + 127) / 128, (KSENT + 127) / 128);
        sgemm_nt<<<grid, 256>>>(senc, saW, sab, gates, KSENT, 200, 200, 200);
    }
    tanh_dot<<<(KSENT + 7) / 8, 256>>>(gates, sactx, scores, KSENT);
    sent_attn<<<KB, 256>>>(scores, senc, dvec);
    classifier<<<KB, 32>>>(dvec, fcW, fcb, out);
}

// round 6
// speedup vs baseline: 1.0016x; 1.0016x over previous
#include <cuda_runtime.h>
#include <cstddef>
#include <cstdint>

// ---------------- problem constants ----------------
#define KVOCAB 100000
#define KED    200
#define KH     100      // HW == HS == 100
#define KNC    10
#define KB     128
#define KS     40
#define KW     50
#define KSENT  (KB * KS)          // 5120

// ---------------- scratch (__device__ globals; no allocations allowed) ----
__device__ float g_gates[(size_t)KVOCAB * 600];   // 240 MB, reused as U buffer & sentence gates
__device__ float g_wenc[(size_t)KVOCAB * 200];    // 80 MB: per-vocab word encoding table
__device__ float g_scorew[KVOCAB];                // per-vocab word attention score
__device__ float g_svec[KSENT * 200];
__device__ float g_senc[KSENT * 200];
__device__ float g_scores[KSENT];
__device__ float g_dvec[KB * 200];
__device__ float g_WcatW[600 * KED];              // [w_Wih_f ; w_Wih_b]
__device__ float g_bihW[600];
__device__ float g_WcatS[600 * 200];              // [s_Wih_f ; s_Wih_b]
__device__ float g_bihS[600];

// ---------------- f32x2 helpers (FFMA2: ptxas never emits this from C++) ---
__device__ __forceinline__ unsigned long long pack2(float lo, float hi) {
    unsigned long long r;
    asm("mov.b64 %0, {%1, %2};" : "=l"(r) : "f"(lo), "f"(hi));
    return r;
}
__device__ __forceinline__ void unpack2(unsigned long long v, float& lo, float& hi) {
    asm("mov.b64 {%0, %1}, %2;" : "=f"(lo), "=f"(hi) : "l"(v));
}
__device__ __forceinline__ void ffma2(unsigned long long& d, unsigned long long a, unsigned long long b) {
    asm("fma.rn.f32x2 %0, %1, %2, %0;" : "+l"(d) : "l"(a), "l"(b));
}
__device__ __forceinline__ float fast_tanh(float x) {
    float y; asm("tanh.approx.f32 %0, %1;" : "=f"(y) : "f"(x)); return y;
}
__device__ __forceinline__ float sigmf(float x) {
    return 0.5f * fast_tanh(0.5f * x) + 0.5f;
}

// ---------------- SGEMM (NT): C[M,N] = A[M,K] * B[N,K]^T + bias[n] --------
// A row-major lda=K, B row-major ldb=K (both K-contiguous), C row-major ldc.
// Requires K % 8 == 0 (K is always 200 here). 128x128x8 tile, double-buffered,
// 256 threads, 8x8 per-thread tile, inner product in packed f32x2 FMAs.
__global__ __launch_bounds__(256)
void sgemm_nt(const float* __restrict__ A, const float* __restrict__ Bm,
              const float* __restrict__ bias, float* __restrict__ C,
              int M, int N, int K, int ldc)
{
    const int BM = 128, BN = 128, BK = 8, TM = 8, TN = 8;
    __shared__ float As[2][BK][BM];
    __shared__ float Bs[2][BK][BN];

    const int tid   = threadIdx.x;
    const int mBase = blockIdx.y * BM;
    const int nBase = blockIdx.x * BN;
    const int lrow  = tid >> 1;          // 0..127
    const int lcol  = (tid & 1) << 2;    // 0 or 4
    const int tx    = tid & 15;
    const int ty    = tid >> 4;
    const int tm0   = ty * TM;
    const int tn0   = tx * TN;

    unsigned long long acc[TM / 2][TN];
#pragma unroll
    for (int i = 0; i < TM / 2; i++)
#pragma unroll
        for (int j = 0; j < TN; j++) acc[i][j] = 0ull;

    const int nk = K >> 3;

    // prologue: stage tile 0
    {
        float4 va = make_float4(0.f, 0.f, 0.f, 0.f);
        float4 vb = make_float4(0.f, 0.f, 0.f, 0.f);
        int m = mBase + lrow;
        if (m < M) va = *reinterpret_cast<const float4*>(A + (size_t)m * K + lcol);
        int n = nBase + lrow;
        if (n < N) vb = *reinterpret_cast<const float4*>(Bm + (size_t)n * K + lcol);
        As[0][lcol + 0][lrow] = va.x; As[0][lcol + 1][lrow] = va.y;
        As[0][lcol + 2][lrow] = va.z; As[0][lcol + 3][lrow] = va.w;
        Bs[0][lcol + 0][lrow] = vb.x; Bs[0][lcol + 1][lrow] = vb.y;
        Bs[0][lcol + 2][lrow] = vb.z; Bs[0][lcol + 3][lrow] = vb.w;
    }
    __syncthreads();

    for (int kt = 0; kt < nk; kt++) {
        const int cur = kt & 1;
        float4 va = make_float4(0.f, 0.f, 0.f, 0.f);
        float4 vb = make_float4(0.f, 0.f, 0.f, 0.f);
        const bool hasNext = (kt + 1 < nk);
        if (hasNext) {
            int k = (kt + 1) * BK + lcol;
            int m = mBase + lrow;
            if (m < M) va = *reinterpret_cast<const float4*>(A + (size_t)m * K + k);
            int n = nBase + lrow;
            if (n < N) vb = *reinterpret_cast<const float4*>(Bm + (size_t)n * K + k);
        }
#pragma unroll
        for (int kk = 0; kk < BK; kk++) {
            float af[TM], bf[TN];
#pragma unroll
            for (int i = 0; i < TM; i++) af[i] = As[cur][kk][tm0 + i];
#pragma unroll
            for (int j = 0; j < TN; j++) bf[j] = Bs[cur][kk][tn0 + j];
            unsigned long long a2[TM / 2], b2[TN];
#pragma unroll
            for (int i = 0; i < TM / 2; i++) a2[i] = pack2(af[2 * i], af[2 * i + 1]);
#pragma unroll
            for (int j = 0; j < TN; j++) b2[j] = pack2(bf[j], bf[j]);
#pragma unroll
            for (int i = 0; i < TM / 2; i++)
#pragma unroll
                for (int j = 0; j < TN; j++) ffma2(acc[i][j], a2[i], b2[j]);
        }
        if (hasNext) {
            const int nxt = cur ^ 1;
            As[nxt][lcol + 0][lrow] = va.x; As[nxt][lcol + 1][lrow] = va.y;
            As[nxt][lcol + 2][lrow] = va.z; As[nxt][lcol + 3][lrow] = va.w;
            Bs[nxt][lcol + 0][lrow] = vb.x; Bs[nxt][lcol + 1][lrow] = vb.y;
            Bs[nxt][lcol + 2][lrow] = vb.z; Bs[nxt][lcol + 3][lrow] = vb.w;
            __syncthreads();
        }
    }

    // epilogue: unpack pairs (rows tm0+2i, tm0+2i+1), add bias, guarded store
#pragma unroll
    for (int i = 0; i < TM / 2; i++) {
#pragma unroll
        for (int j = 0; j < TN; j++) {
            float lo, hi;
            unpack2(acc[i][j], lo, hi);
            int n = nBase + tn0 + j;
            if (n < N) {
                float bv = bias[n];
                int m0 = mBase + tm0 + 2 * i;
                if (m0 < M)     C[(size_t)m0 * ldc + n]       = lo + bv;
                if (m0 + 1 < M) C[(size_t)(m0 + 1) * ldc + n] = hi + bv;
            }
        }
    }
}

// ---------------- GRU-from-zero pointwise -------------------------------
// gates layout per row (ldc=600): [r_f z_f n_f | r_b z_b n_b] (100 each),
// bih already added by the GEMM. h[m] = concat(h_f, h_b) (200).
__global__ void gru_pointwise(const float* __restrict__ g,
                              const float* __restrict__ bhh_f,
                              const float* __restrict__ bhh_b,
                              float* __restrict__ h, int M)
{
    int i = blockIdx.x * blockDim.x + threadIdx.x;
    if (i >= M * KH) return;
    int m = i / KH;
    int d = i - m * KH;
    const float* gr = g + (size_t)m * 600;
    float rf = sigmf(gr[d]       + bhh_f[d]);
    float zf = sigmf(gr[100 + d] + bhh_f[100 + d]);
    float nf = fast_tanh(gr[200 + d] + rf * bhh_f[200 + d]);
    float rb = sigmf(gr[300 + d] + bhh_b[d]);
    float zb = sigmf(gr[400 + d] + bhh_b[100 + d]);
    float nb = fast_tanh(gr[500 + d] + rb * bhh_b[200 + d]);
    float* hr = h + (size_t)m * 200;
    hr[d]       = (1.0f - zf) * nf;
    hr[100 + d] = (1.0f - zb) * nb;
}

// ---------------- score[m] = sum_d ctx[d] * tanh(U[m,d]) (U has bias) ----
__global__ void tanh_dot(const float* __restrict__ U, const float* __restrict__ ctx,
                         float* __restrict__ score, int M)
{
    int warp = (int)((blockIdx.x * blockDim.x + threadIdx.x) >> 5);
    int lane = threadIdx.x & 31;
    if (warp >= M) return;
    const float* u = U + (size_t)warp * 200;
    float s = 0.f;
    for (int d = lane; d < 200; d += 32) s += ctx[d] * fast_tanh(u[d]);
#pragma unroll
    for (int o = 16; o; o >>= 1) s += __shfl_xor_sync(0xffffffffu, s, o);
    if (lane == 0) score[warp] = s;
}

// ---------------- word attention combine: one block per sentence ---------
__global__ void word_attn(const int* __restrict__ x, const float* __restrict__ scoretab,
                          const float* __restrict__ wenc, float* __restrict__ svec)
{
    int s = blockIdx.x;                 // 0..KSENT-1
    __shared__ int   ids[KW];
    __shared__ float al[KW];
    __shared__ float sinv;
    int t = threadIdx.x;                // 256 threads
    if (t < KW) {
        int id = x[s * KW + t];
        ids[t] = id;
        al[t]  = scoretab[id];
    }
    __syncthreads();
    if (t == 0) {
        float mx = -1e30f;
        for (int w = 0; w < KW; w++) mx = fmaxf(mx, al[w]);
        float sum = 0.f;
        for (int w = 0; w < KW; w++) { float e = __expf(al[w] - mx); al[w] = e; sum += e; }
        sinv = 1.0f / sum;
    }
    __syncthreads();
    if (t < 200) {
        float acc = 0.f;
        float inv = sinv;
#pragma unroll 5
        for (int w = 0; w < KW; w++) acc += al[w] * wenc[(size_t)ids[w] * 200 + t];
        svec[(size_t)s * 200 + t] = acc * inv;
    }
}

// ---------------- sentence attention combine: one block per batch row ----
__global__ void sent_attn(const float* __restrict__ scoretab, const float* __restrict__ senc,
                          float* __restrict__ dvec)
{
    int b = blockIdx.x;
    __shared__ float al[KS];
    __shared__ float sinv;
    int t = threadIdx.x;
    if (t < KS) al[t] = scoretab[b * KS + t];
    __syncthreads();
    if (t == 0) {
        float mx = -1e30f;
        for (int i = 0; i < KS; i++) mx = fmaxf(mx, al[i]);
        float sum = 0.f;
        for (int i = 0; i < KS; i++) { float e = __expf(al[i] - mx); al[i] = e; sum += e; }
        sinv = 1.0f / sum;
    }
    __syncthreads();
    if (t < 200) {
        float acc = 0.f;
        float inv = sinv;
#pragma unroll 4
        for (int i = 0; i < KS; i++) acc += al[i] * senc[(size_t)(b * KS + i) * 200 + t];
        dvec[b * 200 + t] = acc * inv;
    }
}

// ---------------- classifier + log_softmax: one warp per batch row -------
__global__ void classifier(const float* __restrict__ dvec, const float* __restrict__ fcW,
                           const float* __restrict__ fcb, float* __restrict__ out)
{
    int b = blockIdx.x;
    int lane = threadIdx.x;             // 32 threads
    const float* dv = dvec + b * 200;
    float logit[KNC];
#pragma unroll
    for (int c = 0; c < KNC; c++) {
        float s = 0.f;
        for (int d = lane; d < 200; d += 32) s += dv[d] * fcW[c * 200 + d];
#pragma unroll
        for (int o = 16; o; o >>= 1) s += __shfl_xor_sync(0xffffffffu, s, o);
        logit[c] = s + fcb[c];          // xor-reduce -> all lanes hold the sum
    }
    if (lane == 0) {
        float mx = -1e30f;
        for (int c = 0; c < KNC; c++) mx = fmaxf(mx, logit[c]);
        float sum = 0.f;
        for (int c = 0; c < KNC; c++) sum += expf(logit[c] - mx);
        float lse = mx + logf(sum);
        for (int c = 0; c < KNC; c++) out[b * KNC + c] = logit[c] - lse;
    }
}

// ---------------- launch --------------------------------------------------
extern "C" void kernel_launch(void* const* d_in, const int* in_sizes, int n_in,
                              void* d_out, int out_size)
{
    (void)in_sizes; (void)n_in; (void)out_size;
    const int*   x     = (const int*)  d_in[0];
    const float* emb   = (const float*)d_in[1];
    const float* wWihf = (const float*)d_in[2];
    const float* wbihf = (const float*)d_in[3];
    const float* wbhhf = (const float*)d_in[4];
    const float* wWihb = (const float*)d_in[5];
    const float* wbihb = (const float*)d_in[6];
    const float* wbhhb = (const float*)d_in[7];
    const float* waW   = (const float*)d_in[8];
    const float* wab   = (const float*)d_in[9];
    const float* wactx = (const float*)d_in[10];
    const float* sWihf = (const float*)d_in[11];
    const float* sbihf = (const float*)d_in[12];
    const float* sbhhf = (const float*)d_in[13];
    const float* sWihb = (const float*)d_in[14];
    const float* sbihb = (const float*)d_in[15];
    const float* sbhhb = (const float*)d_in[16];
    const float* saW   = (const float*)d_in[17];
    const float* sab   = (const float*)d_in[18];
    const float* sactx = (const float*)d_in[19];
    const float* fcW   = (const float*)d_in[20];
    const float* fcb   = (const float*)d_in[21];
    float* out = (float*)d_out;

    float *gates, *wenc, *scorew, *svec, *senc, *scores, *dvec;
    float *WcatW, *bihW, *WcatS, *bihS;
    cudaGetSymbolAddress((void**)&gates,  g_gates);
    cudaGetSymbolAddress((void**)&wenc,   g_wenc);
    cudaGetSymbolAddress((void**)&scorew, g_scorew);
    cudaGetSymbolAddress((void**)&svec,   g_svec);
    cudaGetSymbolAddress((void**)&senc,   g_senc);
    cudaGetSymbolAddress((void**)&scores, g_scores);
    cudaGetSymbolAddress((void**)&dvec,   g_dvec);
    cudaGetSymbolAddress((void**)&WcatW,  g_WcatW);
    cudaGetSymbolAddress((void**)&bihW,   g_bihW);
    cudaGetSymbolAddress((void**)&WcatS,  g_WcatS);
    cudaGetSymbolAddress((void**)&bihS,   g_bihS);

    // concat fwd/bwd input weights & biases (capture-safe D2D copies)
    cudaMemcpyAsync(WcatW,            wWihf, (size_t)300 * KED * sizeof(float), cudaMemcpyDeviceToDevice, 0);
    cudaMemcpyAsync(WcatW + 300 * KED, wWihb, (size_t)300 * KED * sizeof(float), cudaMemcpyDeviceToDevice, 0);
    cudaMemcpyAsync(bihW,       wbihf, 300 * sizeof(float), cudaMemcpyDeviceToDevice, 0);
    cudaMemcpyAsync(bihW + 300, wbihb, 300 * sizeof(float), cudaMemcpyDeviceToDevice, 0);
    cudaMemcpyAsync(WcatS,            sWihf, (size_t)300 * 200 * sizeof(float), cudaMemcpyDeviceToDevice, 0);
    cudaMemcpyAsync(WcatS + 300 * 200, sWihb, (size_t)300 * 200 * sizeof(float), cudaMemcpyDeviceToDevice, 0);
    cudaMemcpyAsync(bihS,       sbihf, 300 * sizeof(float), cudaMemcpyDeviceToDevice, 0);
    cudaMemcpyAsync(bihS + 300, sbihb, 300 * sizeof(float), cudaMemcpyDeviceToDevice, 0);

    // --- word stage (per-vocab tables; tokens only gather) ---
    {   // gates = emb @ WcatW^T + bihW          [VOCAB, 600]
        dim3 grid((600 + 127) / 128, (KVOCAB + 127) / 128);
        sgemm_nt<<<grid, 256>>>(emb, WcatW, bihW, gates, KVOCAB, 600, KED, 600);
    }
    gru_pointwise<<<(KVOCAB * KH + 255) / 256, 256>>>(gates, wbhhf, wbhhb, wenc, KVOCAB);
    {   // U = wenc @ waW^T + wab (reuse gates buffer)   [VOCAB, 200]
        dim3 grid((200 + 127) / 128, (KVOCAB + 127) / 128);
        sgemm_nt<<<grid, 256>>>(wenc, waW, wab, gates, KVOCAB, 200, 200, 200);
    }
    tanh_dot<<<(KVOCAB + 7) / 8, 256>>>(gates, wactx, scorew, KVOCAB);
    word_attn<<<KSENT, 256>>>(x, scorew, wenc, svec);

    // --- sentence stage ---
    {   // gates_s = svec @ WcatS^T + bihS       [5120, 600]
        dim3 grid((600 + 127) / 128, (KSENT + 127) / 128);
        sgemm_nt<<<grid, 256>>>(svec, WcatS, bihS, gates, KSENT, 600, 200, 600);
    }
    gru_pointwise<<<(KSENT * KH + 255) / 256, 256>>>(gates, sbhhf, sbhhb, senc, KSENT);
    {   // U_s = senc @ saW^T + sab              [5120, 200]
        dim3 grid((200 + 127) / 128, (KSENT + 127) / 128);
        sgemm_nt<<<grid, 256>>>(senc, saW, sab, gates, KSENT, 200, 200, 200);
    }
    tanh_dot<<<(KSENT + 7) / 8, 256>>>(gates, sactx, scores, KSENT);
    sent_attn<<<KB, 256>>>(scores, senc, dvec);
    classifier<<<KB, 32>>>(dvec, fcW, fcb, out);
}

// round 7
// speedup vs baseline: 1.9173x; 1.9142x over previous
#include <cuda_runtime.h>
#include <cuda_bf16.h>
#include <cstddef>
#include <cstdint>

// ---------------- problem constants ----------------
#define KVOCAB 100000
#define KED    200
#define KH     100      // HW == HS == 100
#define KNC    10
#define KB     128
#define KS     40
#define KW     50
#define KSENT  (KB * KS)          // 5120

#define KP     208      // K padded (13 * 16)
#define NG     608      // GRU gate width padded (600 -> 608)
#define NA     224      // attention proj width padded (200 -> 224)

// ---------------- scratch (__device__ globals; no allocations allowed) ----
__device__ __nv_bfloat16 g_embBF[(size_t)KVOCAB * KP];   // 41.6 MB
__device__ __nv_bfloat16 g_wencBF[(size_t)KVOCAB * KP];  // 41.6 MB
__device__ float         g_scorew[KVOCAB];
__device__ __nv_bfloat16 g_svecBF[KSENT * KP];
__device__ float         g_sencF[KSENT * 200];
__device__ __nv_bfloat16 g_sencBF[KSENT * KP];
__device__ float         g_scores[KSENT];
__device__ float         g_dvec[KB * 200];
__device__ __nv_bfloat16 g_WgruW[NG * KP];
__device__ __nv_bfloat16 g_WgruS[NG * KP];
__device__ __nv_bfloat16 g_WattnW[NA * KP];
__device__ __nv_bfloat16 g_WattnS[NA * KP];

// ---------------- math helpers -------------------------------------------
__device__ __forceinline__ float fast_tanh(float x) {
    float y; asm("tanh.approx.f32 %0, %1;" : "=f"(y) : "f"(x)); return y;
}
__device__ __forceinline__ float sigmf(float x) {
    return 0.5f * fast_tanh(0.5f * x) + 0.5f;
}
__device__ __forceinline__ void mma_bf16(float c[4],
    uint32_t a0, uint32_t a1, uint32_t a2, uint32_t a3, uint32_t b0, uint32_t b1)
{
    asm volatile(
        "mma.sync.aligned.m16n8k16.row.col.f32.bf16.bf16.f32 "
        "{%0,%1,%2,%3}, {%4,%5,%6,%7}, {%8,%9}, {%0,%1,%2,%3};"
        : "+f"(c[0]), "+f"(c[1]), "+f"(c[2]), "+f"(c[3])
        : "r"(a0), "r"(a1), "r"(a2), "r"(a3), "r"(b0), "r"(b1));
}

// ---------------- prep kernels -------------------------------------------
// fp32 [M][200] -> bf16 [M][208] with zero K-pad
__global__ void conv_pad(const float* __restrict__ src, __nv_bfloat16* __restrict__ dst, int M)
{
    int i = blockIdx.x * blockDim.x + threadIdx.x;
    if (i >= M * KP) return;
    int m = i / KP, c = i - m * KP;
    dst[i] = __float2bfloat16(c < 200 ? src[(size_t)m * 200 + c] : 0.f);
}
// [wf(300x200); wb(300x200)] -> bf16 [608][208]
__global__ void prep_gruW(const float* __restrict__ wf, const float* __restrict__ wb,
                          __nv_bfloat16* __restrict__ dst)
{
    int i = blockIdx.x * blockDim.x + threadIdx.x;
    if (i >= NG * KP) return;
    int r = i / KP, c = i - r * KP;
    float v = 0.f;
    if (c < 200) {
        if (r < 300)      v = wf[r * 200 + c];
        else if (r < 600) v = wb[(r - 300) * 200 + c];
    }
    dst[i] = __float2bfloat16(v);
}
// [200][200] -> bf16 [224][208]
__global__ void prep_attnW(const float* __restrict__ w, __nv_bfloat16* __restrict__ dst)
{
    int i = blockIdx.x * blockDim.x + threadIdx.x;
    if (i >= NA * KP) return;
    int r = i / KP, c = i - r * KP;
    float v = (r < 200 && c < 200) ? w[r * 200 + c] : 0.f;
    dst[i] = __float2bfloat16(v);
}

// ---------------- fused GEMM(bf16 mma) + GRU-from-zero --------------------
// A [M][208] bf16, W [608][208] bf16 (row n = gate col n), biases fp32.
// Block: 512 thr (16 warps: 4 M x 4 N), M-tile 64, full N=608, K=208.
// Epilogue: gates staged in dyn smem, GRU applied, h written (fp32 optional + bf16 padded).
__global__ __launch_bounds__(512)
void fused_gru_gemm(const __nv_bfloat16* __restrict__ A, const __nv_bfloat16* __restrict__ W,
                    const float* __restrict__ bihf, const float* __restrict__ bhhf,
                    const float* __restrict__ bihb, const float* __restrict__ bhhb,
                    float* __restrict__ hF, __nv_bfloat16* __restrict__ hBF, int M)
{
    extern __shared__ char smraw[];
    uint32_t* Bs = (uint32_t*)smraw;          // 608*8 words
    uint32_t* As = Bs + NG * 8;               // 64*8 words
    float*    Sg = (float*)smraw;             // epilogue: 64*608 fp32 (aliases)

    const int tid = threadIdx.x, wid = tid >> 5, lane = tid & 31;
    const int gq = lane >> 2, qp = lane & 3;
    const int mW = wid >> 2, nW = wid & 3;
    const int mBase = blockIdx.x * 64;

    float acc[19][4];
#pragma unroll
    for (int t = 0; t < 19; t++) { acc[t][0] = acc[t][1] = acc[t][2] = acc[t][3] = 0.f; }

    for (int kt = 0; kt < 13; kt++) {
        const int k0 = kt * 16;
        {   // A tile 64x16 bf16 = 512 words, 1/thread
            int r = tid >> 3, c2 = tid & 7;
            int gm = mBase + r;
            uint32_t v = 0;
            if (gm < M) v = *(const uint32_t*)(A + (size_t)gm * KP + k0 + c2 * 2);
            As[r * 8 + c2] = v;
        }
        for (int j = tid; j < NG * 8; j += 512) {   // B tile 608x16 bf16
            int n = j >> 3, c2 = j & 7;
            Bs[j] = *(const uint32_t*)(W + (size_t)n * KP + k0 + c2 * 2);
        }
        __syncthreads();
        const int ar = mW * 16 + gq;
        uint32_t a0 = As[ar * 8 + qp];
        uint32_t a1 = As[(ar + 8) * 8 + qp];
        uint32_t a2 = As[ar * 8 + 4 + qp];
        uint32_t a3 = As[(ar + 8) * 8 + 4 + qp];
#pragma unroll
        for (int t = 0; t < 19; t++) {
            int n0 = nW * 152 + t * 8 + gq;
            uint32_t b0 = Bs[n0 * 8 + qp];
            uint32_t b1 = Bs[n0 * 8 + 4 + qp];
            mma_bf16(acc[t], a0, a1, a2, a3, b0, b1);
        }
        __syncthreads();
    }

    // stage gate tile to smem
#pragma unroll
    for (int t = 0; t < 19; t++) {
        int r = mW * 16 + gq, c = nW * 152 + t * 8 + qp * 2;
        Sg[r * NG + c]           = acc[t][0];
        Sg[r * NG + c + 1]       = acc[t][1];
        Sg[(r + 8) * NG + c]     = acc[t][2];
        Sg[(r + 8) * NG + c + 1] = acc[t][3];
    }
    __syncthreads();

    // GRU pointwise from smem: cols [0:100)=r_f [100:200)=z_f [200:300)=n_f, bwd +300
    for (int i = tid; i < 64 * KH; i += 512) {
        int m = i / KH, d = i - m * KH;
        int gm = mBase + m;
        if (gm >= M) continue;
        const float* row = Sg + m * NG;
        float rf = sigmf(row[d]       + __ldg(bihf + d)       + __ldg(bhhf + d));
        float zf = sigmf(row[100 + d] + __ldg(bihf + 100 + d) + __ldg(bhhf + 100 + d));
        float nf = fast_tanh(row[200 + d] + __ldg(bihf + 200 + d) + rf * __ldg(bhhf + 200 + d));
        float hf = (1.f - zf) * nf;
        float rb = sigmf(row[300 + d] + __ldg(bihb + d)       + __ldg(bhhb + d));
        float zb = sigmf(row[400 + d] + __ldg(bihb + 100 + d) + __ldg(bhhb + 100 + d));
        float nb = fast_tanh(row[500 + d] + __ldg(bihb + 200 + d) + rb * __ldg(bhhb + 200 + d));
        float hb = (1.f - zb) * nb;
        if (hF) { hF[(size_t)gm * 200 + d] = hf; hF[(size_t)gm * 200 + 100 + d] = hb; }
        hBF[(size_t)gm * KP + d]       = __float2bfloat16(hf);
        hBF[(size_t)gm * KP + 100 + d] = __float2bfloat16(hb);
    }
    for (int j = tid; j < 64 * 8; j += 512) {   // zero the K-pad columns
        int m = j >> 3, gm = mBase + m;
        if (gm < M) hBF[(size_t)gm * KP + 200 + (j & 7)] = __float2bfloat16(0.f);
    }
}

// ---------------- fused GEMM(bf16 mma) + ctx . tanh(U + b) ----------------
// A [M][208] bf16, W [224][208] bf16; score[m] = sum_{c<200} ctx[c]*tanh(U[m][c]+b[c])
// Block: 256 thr (8 warps: 4 M x 2 N), M-tile 64, N=224, K=208.
__global__ __launch_bounds__(256)
void fused_score(const __nv_bfloat16* __restrict__ A, const __nv_bfloat16* __restrict__ W,
                 const float* __restrict__ bias, const float* __restrict__ ctx,
                 float* __restrict__ score, int M)
{
    __shared__ uint32_t Bs[NA * 8];
    __shared__ uint32_t As[64 * 8];
    __shared__ float ctxs[NA], biass[NA], part[64];

    const int tid = threadIdx.x, wid = tid >> 5, lane = tid & 31;
    const int gq = lane >> 2, qp = lane & 3;
    const int mW = wid >> 1, nW = wid & 1;
    const int mBase = blockIdx.x * 64;

    if (tid < NA) {
        ctxs[tid]  = (tid < 200) ? ctx[tid]  : 0.f;
        biass[tid] = (tid < 200) ? bias[tid] : 0.f;
    }
    if (tid < 64) part[tid] = 0.f;

    float acc[14][4];
#pragma unroll
    for (int t = 0; t < 14; t++) { acc[t][0] = acc[t][1] = acc[t][2] = acc[t][3] = 0.f; }

    for (int kt = 0; kt < 13; kt++) {
        const int k0 = kt * 16;
        for (int j = tid; j < 512; j += 256) {
            int r = j >> 3, c2 = j & 7;
            int gm = mBase + r;
            uint32_t v = 0;
            if (gm < M) v = *(const uint32_t*)(A + (size_t)gm * KP + k0 + c2 * 2);
            As[j] = v;
        }
        for (int j = tid; j < NA * 8; j += 256) {
            int n = j >> 3, c2 = j & 7;
            Bs[j] = *(const uint32_t*)(W + (size_t)n * KP + k0 + c2 * 2);
        }
        __syncthreads();
        const int ar = mW * 16 + gq;
        uint32_t a0 = As[ar * 8 + qp];
        uint32_t a1 = As[(ar + 8) * 8 + qp];
        uint32_t a2 = As[ar * 8 + 4 + qp];
        uint32_t a3 = As[(ar + 8) * 8 + 4 + qp];
#pragma unroll
        for (int t = 0; t < 14; t++) {
            int n0 = nW * 112 + t * 8 + gq;
            uint32_t b0 = Bs[n0 * 8 + qp];
            uint32_t b1 = Bs[n0 * 8 + 4 + qp];
            mma_bf16(acc[t], a0, a1, a2, a3, b0, b1);
        }
        __syncthreads();
    }

    float l0 = 0.f, l1 = 0.f;
#pragma unroll
    for (int t = 0; t < 14; t++) {
        int c0 = nW * 112 + t * 8 + qp * 2;
        l0 += ctxs[c0]     * fast_tanh(acc[t][0] + biass[c0]);
        l0 += ctxs[c0 + 1] * fast_tanh(acc[t][1] + biass[c0 + 1]);
        l1 += ctxs[c0]     * fast_tanh(acc[t][2] + biass[c0]);
        l1 += ctxs[c0 + 1] * fast_tanh(acc[t][3] + biass[c0 + 1]);
    }
    atomicAdd(&part[mW * 16 + gq],     l0);
    atomicAdd(&part[mW * 16 + gq + 8], l1);
    __syncthreads();
    if (tid < 64 && mBase + tid < M) score[mBase + tid] = part[tid];
}

// ---------------- word attention combine: one block per sentence ---------
__global__ void word_attn(const int* __restrict__ x, const float* __restrict__ scoretab,
                          const __nv_bfloat16* __restrict__ wencBF,
                          __nv_bfloat16* __restrict__ svecBF)
{
    int s = blockIdx.x;
    __shared__ int   ids[KW];
    __shared__ float al[KW];
    __shared__ float sinv;
    int t = threadIdx.x;
    if (t < KW) {
        int id = x[s * KW + t];
        ids[t] = id;
        al[t]  = scoretab[id];
    }
    __syncthreads();
    if (t == 0) {
        float mx = -1e30f;
        for (int w = 0; w < KW; w++) mx = fmaxf(mx, al[w]);
        float sum = 0.f;
        for (int w = 0; w < KW; w++) { float e = __expf(al[w] - mx); al[w] = e; sum += e; }
        sinv = 1.0f / sum;
    }
    __syncthreads();
    if (t < 200) {
        float a = 0.f;
        float inv = sinv;
#pragma unroll 5
        for (int w = 0; w < KW; w++)
            a += al[w] * __bfloat162float(wencBF[(size_t)ids[w] * KP + t]);
        svecBF[(size_t)s * KP + t] = __float2bfloat16(a * inv);
    } else if (t < KP) {
        svecBF[(size_t)s * KP + t] = __float2bfloat16(0.f);
    }
}

// ---------------- sentence attention combine: one block per batch row ----
__global__ void sent_attn(const float* __restrict__ scoretab, const float* __restrict__ senc,
                          float* __restrict__ dvec)
{
    int b = blockIdx.x;
    __shared__ float al[KS];
    __shared__ float sinv;
    int t = threadIdx.x;
    if (t < KS) al[t] = scoretab[b * KS + t];
    __syncthreads();
    if (t == 0) {
        float mx = -1e30f;
        for (int i = 0; i < KS; i++) mx = fmaxf(mx, al[i]);
        float sum = 0.f;
        for (int i = 0; i < KS; i++) { float e = __expf(al[i] - mx); al[i] = e; sum += e; }
        sinv = 1.0f / sum;
    }
    __syncthreads();
    if (t < 200) {
        float a = 0.f;
        float inv = sinv;
#pragma unroll 4
        for (int i = 0; i < KS; i++) a += al[i] * senc[(size_t)(b * KS + i) * 200 + t];
        dvec[b * 200 + t] = a * inv;
    }
}

// ---------------- classifier + log_softmax: one warp per batch row -------
__global__ void classifier(const float* __restrict__ dvec, const float* __restrict__ fcW,
                           const float* __restrict__ fcb, float* __restrict__ out)
{
    int b = blockIdx.x;
    int lane = threadIdx.x;
    const float* dv = dvec + b * 200;
    float logit[KNC];
#pragma unroll
    for (int c = 0; c < KNC; c++) {
        float s = 0.f;
        for (int d = lane; d < 200; d += 32) s += dv[d] * fcW[c * 200 + d];
#pragma unroll
        for (int o = 16; o; o >>= 1) s += __shfl_xor_sync(0xffffffffu, s, o);
        logit[c] = s + fcb[c];
    }
    if (lane == 0) {
        float mx = -1e30f;
        for (int c = 0; c < KNC; c++) mx = fmaxf(mx, logit[c]);
        float sum = 0.f;
        for (int c = 0; c < KNC; c++) sum += expf(logit[c] - mx);
        float lse = mx + logf(sum);
        for (int c = 0; c < KNC; c++) out[b * KNC + c] = logit[c] - lse;
    }
}

// ---------------- launch --------------------------------------------------
extern "C" void kernel_launch(void* const* d_in, const int* in_sizes, int n_in,
                              void* d_out, int out_size)
{
    (void)in_sizes; (void)n_in; (void)out_size;
    const int*   x     = (const int*)  d_in[0];
    const float* emb   = (const float*)d_in[1];
    const float* wWihf = (const float*)d_in[2];
    const float* wbihf = (const float*)d_in[3];
    const float* wbhhf = (const float*)d_in[4];
    const float* wWihb = (const float*)d_in[5];
    const float* wbihb = (const float*)d_in[6];
    const float* wbhhb = (const float*)d_in[7];
    const float* waW   = (const float*)d_in[8];
    const float* wab   = (const float*)d_in[9];
    const float* wactx = (const float*)d_in[10];
    const float* sWihf = (const float*)d_in[11];
    const float* sbihf = (const float*)d_in[12];
    const float* sbhhf = (const float*)d_in[13];
    const float* sWihb = (const float*)d_in[14];
    const float* sbihb = (const float*)d_in[15];
    const float* sbhhb = (const float*)d_in[16];
    const float* saW   = (const float*)d_in[17];
    const float* sab   = (const float*)d_in[18];
    const float* sactx = (const float*)d_in[19];
    const float* fcW   = (const float*)d_in[20];
    const float* fcb   = (const float*)d_in[21];
    float* out = (float*)d_out;

    __nv_bfloat16 *embBF, *wencBF, *svecBF, *sencBF, *WgruW, *WgruS, *WattnW, *WattnS;
    float *scorew, *sencF, *scores, *dvec;
    cudaGetSymbolAddress((void**)&embBF,  g_embBF);
    cudaGetSymbolAddress((void**)&wencBF, g_wencBF);
    cudaGetSymbolAddress((void**)&scorew, g_scorew);
    cudaGetSymbolAddress((void**)&svecBF, g_svecBF);
    cudaGetSymbolAddress((void**)&sencF,  g_sencF);
    cudaGetSymbolAddress((void**)&sencBF, g_sencBF);
    cudaGetSymbolAddress((void**)&scores, g_scores);
    cudaGetSymbolAddress((void**)&dvec,   g_dvec);
    cudaGetSymbolAddress((void**)&WgruW,  g_WgruW);
    cudaGetSymbolAddress((void**)&WgruS,  g_WgruS);
    cudaGetSymbolAddress((void**)&WattnW, g_WattnW);
    cudaGetSymbolAddress((void**)&WattnS, g_WattnS);

    const int GRU_SMEM = 64 * NG * 4;   // 155648 B (>= loop staging 21.5 KB)
    cudaFuncSetAttribute(fused_gru_gemm, cudaFuncAttributeMaxDynamicSharedMemorySize, GRU_SMEM);

    // prep: bf16 conversions with K/N padding
    conv_pad<<<(KVOCAB * KP + 255) / 256, 256>>>(emb, embBF, KVOCAB);
    prep_gruW<<<(NG * KP + 255) / 256, 256>>>(wWihf, wWihb, WgruW);
    prep_gruW<<<(NG * KP + 255) / 256, 256>>>(sWihf, sWihb, WgruS);
    prep_attnW<<<(NA * KP + 255) / 256, 256>>>(waW, WattnW);
    prep_attnW<<<(NA * KP + 255) / 256, 256>>>(saW, WattnS);

    // word stage (per-vocab tables)
    fused_gru_gemm<<<(KVOCAB + 63) / 64, 512, GRU_SMEM>>>(
        embBF, WgruW, wbihf, wbhhf, wbihb, wbhhb, nullptr, wencBF, KVOCAB);
    fused_score<<<(KVOCAB + 63) / 64, 256>>>(wencBF, WattnW, wab, wactx, scorew, KVOCAB);
    word_attn<<<KSENT, 256>>>(x, scorew, wencBF, svecBF);

    // sentence stage
    fused_gru_gemm<<<(KSENT + 63) / 64, 512, GRU_SMEM>>>(
        svecBF, WgruS, sbihf, sbhhf, sbihb, sbhhb, sencF, sencBF, KSENT);
    fused_score<<<(KSENT + 63) / 64, 256>>>(sencBF, WattnS, sab, sactx, scores, KSENT);
    sent_attn<<<KB, 256>>>(scores, sencF, dvec);
    classifier<<<KB, 32>>>(dvec, fcW, fcb, out);
}

// round 8
// speedup vs baseline: 3.1837x; 1.6605x over previous
#include <cuda_runtime.h>
#include <cuda_bf16.h>
#include <cstddef>
#include <cstdint>

// ---------------- problem constants ----------------
#define KVOCAB 100000
#define KED    200
#define KH     100      // HW == HS == 100
#define KNC    10
#define KB     128
#define KS     40
#define KW     50
#define KSENT  (KB * KS)          // 5120

#define KP     208      // K padded (13 * 16)
#define NG     608      // GRU gate width padded (600 -> 608)
#define NA     224      // attention proj width padded (200 -> 224)
#define SGS    616      // epilogue staging stride (608+8: breaks %32==0 bank aliasing)

// ---------------- scratch (__device__ globals; no allocations allowed) ----
__device__ __nv_bfloat16 g_embBF[(size_t)KVOCAB * KP];   // 41.6 MB
__device__ __nv_bfloat16 g_wencBF[(size_t)KVOCAB * KP];  // 41.6 MB
__device__ float         g_scorew[KVOCAB];
__device__ __nv_bfloat16 g_svecBF[KSENT * KP];
__device__ float         g_sencF[KSENT * 200];
__device__ __nv_bfloat16 g_sencBF[KSENT * KP];
__device__ float         g_scores[KSENT];
__device__ float         g_dvec[KB * 200];
__device__ __nv_bfloat16 g_WgruW[NG * KP];
__device__ __nv_bfloat16 g_WgruS[NG * KP];
__device__ __nv_bfloat16 g_WattnW[NA * KP];
__device__ __nv_bfloat16 g_WattnS[NA * KP];

// ---------------- math / ptx helpers --------------------------------------
__device__ __forceinline__ float fast_tanh(float x) {
    float y; asm("tanh.approx.f32 %0, %1;" : "=f"(y) : "f"(x)); return y;
}
__device__ __forceinline__ float sigmf(float x) {
    return 0.5f * fast_tanh(0.5f * x) + 0.5f;
}
__device__ __forceinline__ void mma_bf16(float c[4],
    uint32_t a0, uint32_t a1, uint32_t a2, uint32_t a3, uint32_t b0, uint32_t b1)
{
    asm volatile(
        "mma.sync.aligned.m16n8k16.row.col.f32.bf16.bf16.f32 "
        "{%0,%1,%2,%3}, {%4,%5,%6,%7}, {%8,%9}, {%0,%1,%2,%3};"
        : "+f"(c[0]), "+f"(c[1]), "+f"(c[2]), "+f"(c[3])
        : "r"(a0), "r"(a1), "r"(a2), "r"(a3), "r"(b0), "r"(b1));
}
__device__ __forceinline__ void cp16(void* dst_smem, const void* src, bool ok) {
    uint32_t d = (uint32_t)__cvta_generic_to_shared(dst_smem);
    int sz = ok ? 16 : 0;
    asm volatile("cp.async.cg.shared.global [%0], [%1], 16, %2;"
                 :: "r"(d), "l"(src), "r"(sz) : "memory");
}
__device__ __forceinline__ void cp_commit() {
    asm volatile("cp.async.commit_group;" ::: "memory");
}
template <int N>
__device__ __forceinline__ void cp_wait() {
    asm volatile("cp.async.wait_group %0;" :: "n"(N) : "memory");
}

// ---------------- prep kernels -------------------------------------------
__global__ void conv_pad(const float* __restrict__ src, __nv_bfloat16* __restrict__ dst, int M)
{
    int i = blockIdx.x * blockDim.x + threadIdx.x;
    if (i >= M * KP) return;
    int m = i / KP, c = i - m * KP;
    dst[i] = __float2bfloat16(c < 200 ? src[(size_t)m * 200 + c] : 0.f);
}
__global__ void prep_gruW(const float* __restrict__ wf, const float* __restrict__ wb,
                          __nv_bfloat16* __restrict__ dst)
{
    int i = blockIdx.x * blockDim.x + threadIdx.x;
    if (i >= NG * KP) return;
    int r = i / KP, c = i - r * KP;
    float v = 0.f;
    if (c < 200) {
        if (r < 300)      v = wf[r * 200 + c];
        else if (r < 600) v = wb[(r - 300) * 200 + c];
    }
    dst[i] = __float2bfloat16(v);
}
__global__ void prep_attnW(const float* __restrict__ w, __nv_bfloat16* __restrict__ dst)
{
    int i = blockIdx.x * blockDim.x + threadIdx.x;
    if (i >= NA * KP) return;
    int r = i / KP, c = i - r * KP;
    float v = (r < 200 && c < 200) ? w[r * 200 + c] : 0.f;
    dst[i] = __float2bfloat16(v);
}

// ---------------- fused GEMM(bf16 mma, pipelined) + GRU-from-zero ---------
// Block: 256 thr (8 warps: 2M x 4N). M-tile 64 (32 rows/warp), N=608, K=208.
// cp.async double-buffered tiles; epilogue staged in padded smem (stride 616).
__global__ __launch_bounds__(256, 1)
void fused_gru_gemm(const __nv_bfloat16* __restrict__ A, const __nv_bfloat16* __restrict__ W,
                    const float* __restrict__ bihf, const float* __restrict__ bhhf,
                    const float* __restrict__ bihb, const float* __restrict__ bhhb,
                    float* __restrict__ hF, __nv_bfloat16* __restrict__ hBF, int M)
{
    extern __shared__ __align__(16) char smraw[];
    __nv_bfloat16* BsAll = (__nv_bfloat16*)smraw;       // 2 * 608*16
    __nv_bfloat16* AsAll = BsAll + 2 * NG * 16;         // 2 * 64*16
    float* Sg = (float*)smraw;                           // epilogue 64*616 (aliases)

    const int tid = threadIdx.x, wid = tid >> 5, lane = tid & 31;
    const int gq = lane >> 2, qp = lane & 3;
    const int mW = wid >> 2, nW = wid & 3;               // mW 0..1, nW 0..3
    const int mBase = blockIdx.x * 64;

    float acc[2][19][4];
#pragma unroll
    for (int mi = 0; mi < 2; mi++)
#pragma unroll
        for (int t = 0; t < 19; t++)
#pragma unroll
            for (int q = 0; q < 4; q++) acc[mi][t][q] = 0.f;

    auto loadTiles = [&](int kt, int buf) {
        const int k0 = kt * 16;
        __nv_bfloat16* Bd = BsAll + buf * NG * 16;
        __nv_bfloat16* Ad = AsAll + buf * 64 * 16;
        for (int c = tid; c < NG * 2; c += 256) {        // B: 1216 16B chunks
            int n = c >> 1, h = c & 1;
            cp16(Bd + n * 16 + h * 8, W + (size_t)n * KP + k0 + h * 8, true);
        }
        if (tid < 128) {                                  // A: 128 16B chunks
            int r = tid >> 1, h = tid & 1;
            int gm = mBase + r;
            bool ok = gm < M;
            cp16(Ad + r * 16 + h * 8, A + (size_t)(ok ? gm : 0) * KP + k0 + h * 8, ok);
        }
    };

    loadTiles(0, 0);
    cp_commit();

    for (int kt = 0; kt < 13; kt++) {
        const int buf = kt & 1;
        if (kt + 1 < 13) { loadTiles(kt + 1, buf ^ 1); cp_commit(); cp_wait<1>(); }
        else             { cp_wait<0>(); }
        __syncthreads();

        const uint32_t* AsW = (const uint32_t*)(AsAll + buf * 64 * 16);
        const uint32_t* BsW = (const uint32_t*)(BsAll + buf * NG * 16);
        uint32_t a[2][4];
#pragma unroll
        for (int mi = 0; mi < 2; mi++) {
            int ar = mW * 32 + mi * 16 + gq;
            a[mi][0] = AsW[ar * 8 + qp];
            a[mi][1] = AsW[(ar + 8) * 8 + qp];
            a[mi][2] = AsW[ar * 8 + 4 + qp];
            a[mi][3] = AsW[(ar + 8) * 8 + 4 + qp];
        }
#pragma unroll
        for (int t = 0; t < 19; t++) {
            int n0 = nW * 152 + t * 8 + gq;
            uint32_t b0 = BsW[n0 * 8 + qp];
            uint32_t b1 = BsW[n0 * 8 + 4 + qp];
            mma_bf16(acc[0][t], a[0][0], a[0][1], a[0][2], a[0][3], b0, b1);
            mma_bf16(acc[1][t], a[1][0], a[1][1], a[1][2], a[1][3], b0, b1);
        }
        __syncthreads();
    }

    // stage gate tile (padded stride: 2-way instead of 8-way conflicts)
#pragma unroll
    for (int mi = 0; mi < 2; mi++)
#pragma unroll
    for (int t = 0; t < 19; t++) {
        int r = mW * 32 + mi * 16 + gq, c = nW * 152 + t * 8 + qp * 2;
        Sg[r * SGS + c]           = acc[mi][t][0];
        Sg[r * SGS + c + 1]       = acc[mi][t][1];
        Sg[(r + 8) * SGS + c]     = acc[mi][t][2];
        Sg[(r + 8) * SGS + c + 1] = acc[mi][t][3];
    }
    __syncthreads();

    // GRU pointwise from smem
    for (int i = tid; i < 64 * KH; i += 256) {
        int m = i / KH, d = i - m * KH;
        int gm = mBase + m;
        if (gm >= M) continue;
        const float* row = Sg + m * SGS;
        float rf = sigmf(row[d]       + __ldg(bihf + d)       + __ldg(bhhf + d));
        float zf = sigmf(row[100 + d] + __ldg(bihf + 100 + d) + __ldg(bhhf + 100 + d));
        float nf = fast_tanh(row[200 + d] + __ldg(bihf + 200 + d) + rf * __ldg(bhhf + 200 + d));
        float hf = (1.f - zf) * nf;
        float rb = sigmf(row[300 + d] + __ldg(bihb + d)       + __ldg(bhhb + d));
        float zb = sigmf(row[400 + d] + __ldg(bihb + 100 + d) + __ldg(bhhb + 100 + d));
        float nb = fast_tanh(row[500 + d] + __ldg(bihb + 200 + d) + rb * __ldg(bhhb + 200 + d));
        float hb = (1.f - zb) * nb;
        if (hF) { hF[(size_t)gm * 200 + d] = hf; hF[(size_t)gm * 200 + 100 + d] = hb; }
        hBF[(size_t)gm * KP + d]       = __float2bfloat16(hf);
        hBF[(size_t)gm * KP + 100 + d] = __float2bfloat16(hb);
    }
    for (int j = tid; j < 64 * 8; j += 256) {   // zero the K-pad columns
        int m = j >> 3, gm = mBase + m;
        if (gm < M) hBF[(size_t)gm * KP + 200 + (j & 7)] = __float2bfloat16(0.f);
    }
}

// ---------------- fused GEMM(bf16 mma, pipelined) + ctx . tanh(U + b) ----
// Block: 256 thr (8 warps: 2M x 4N). M-tile 64, N=224 (56 cols/warp), K=208.
__global__ __launch_bounds__(256, 1)
void fused_score(const __nv_bfloat16* __restrict__ A, const __nv_bfloat16* __restrict__ W,
                 const float* __restrict__ bias, const float* __restrict__ ctx,
                 float* __restrict__ score, int M)
{
    __shared__ __align__(16) __nv_bfloat16 BsAll[2 * NA * 16];
    __shared__ __align__(16) __nv_bfloat16 AsAll[2 * 64 * 16];
    __shared__ float ctxs[NA], biass[NA], part[64];

    const int tid = threadIdx.x, wid = tid >> 5, lane = tid & 31;
    const int gq = lane >> 2, qp = lane & 3;
    const int mW = wid >> 2, nW = wid & 3;
    const int mBase = blockIdx.x * 64;

    if (tid < NA) {
        ctxs[tid]  = (tid < 200) ? ctx[tid]  : 0.f;
        biass[tid] = (tid < 200) ? bias[tid] : 0.f;
    }
    if (tid < 64) part[tid] = 0.f;

    float acc[2][7][4];
#pragma unroll
    for (int mi = 0; mi < 2; mi++)
#pragma unroll
        for (int t = 0; t < 7; t++)
#pragma unroll
            for (int q = 0; q < 4; q++) acc[mi][t][q] = 0.f;

    auto loadTiles = [&](int kt, int buf) {
        const int k0 = kt * 16;
        __nv_bfloat16* Bd = BsAll + buf * NA * 16;
        __nv_bfloat16* Ad = AsAll + buf * 64 * 16;
        for (int c = tid; c < NA * 2; c += 256) {
            int n = c >> 1, h = c & 1;
            cp16(Bd + n * 16 + h * 8, W + (size_t)n * KP + k0 + h * 8, true);
        }
        if (tid < 128) {
            int r = tid >> 1, h = tid & 1;
            int gm = mBase + r;
            bool ok = gm < M;
            cp16(Ad + r * 16 + h * 8, A + (size_t)(ok ? gm : 0) * KP + k0 + h * 8, ok);
        }
    };

    loadTiles(0, 0);
    cp_commit();

    for (int kt = 0; kt < 13; kt++) {
        const int buf = kt & 1;
        if (kt + 1 < 13) { loadTiles(kt + 1, buf ^ 1); cp_commit(); cp_wait<1>(); }
        else             { cp_wait<0>(); }
        __syncthreads();

        const uint32_t* AsW = (const uint32_t*)(AsAll + buf * 64 * 16);
        const uint32_t* BsW = (const uint32_t*)(BsAll + buf * NA * 16);
        uint32_t a[2][4];
#pragma unroll
        for (int mi = 0; mi < 2; mi++) {
            int ar = mW * 32 + mi * 16 + gq;
            a[mi][0] = AsW[ar * 8 + qp];
            a[mi][1] = AsW[(ar + 8) * 8 + qp];
            a[mi][2] = AsW[ar * 8 + 4 + qp];
            a[mi][3] = AsW[(ar + 8) * 8 + 4 + qp];
        }
#pragma unroll
        for (int t = 0; t < 7; t++) {
            int n0 = nW * 56 + t * 8 + gq;
            uint32_t b0 = BsW[n0 * 8 + qp];
            uint32_t b1 = BsW[n0 * 8 + 4 + qp];
            mma_bf16(acc[0][t], a[0][0], a[0][1], a[0][2], a[0][3], b0, b1);
            mma_bf16(acc[1][t], a[1][0], a[1][1], a[1][2], a[1][3], b0, b1);
        }
        __syncthreads();
    }

    float l00 = 0.f, l01 = 0.f, l10 = 0.f, l11 = 0.f;
#pragma unroll
    for (int mi = 0; mi < 2; mi++) {
        float s0 = 0.f, s1 = 0.f;
#pragma unroll
        for (int t = 0; t < 7; t++) {
            int c0 = nW * 56 + t * 8 + qp * 2;
            s0 += ctxs[c0]     * fast_tanh(acc[mi][t][0] + biass[c0]);
            s0 += ctxs[c0 + 1] * fast_tanh(acc[mi][t][1] + biass[c0 + 1]);
            s1 += ctxs[c0]     * fast_tanh(acc[mi][t][2] + biass[c0]);
            s1 += ctxs[c0 + 1] * fast_tanh(acc[mi][t][3] + biass[c0 + 1]);
        }
        if (mi == 0) { l00 = s0; l01 = s1; } else { l10 = s0; l11 = s1; }
    }
    atomicAdd(&part[mW * 32 + gq],      l00);
    atomicAdd(&part[mW * 32 + gq + 8],  l01);
    atomicAdd(&part[mW * 32 + 16 + gq], l10);
    atomicAdd(&part[mW * 32 + 24 + gq], l11);
    __syncthreads();
    if (tid < 64 && mBase + tid < M) score[mBase + tid] = part[tid];
}

// ---------------- word attention combine: one block per sentence ---------
__global__ void word_attn(const int* __restrict__ x, const float* __restrict__ scoretab,
                          const __nv_bfloat16* __restrict__ wencBF,
                          __nv_bfloat16* __restrict__ svecBF)
{
    int s = blockIdx.x;
    __shared__ int   ids[KW];
    __shared__ float al[KW];
    __shared__ float sinv;
    int t = threadIdx.x;                 // 128 threads
    if (t < KW) {
        int id = x[s * KW + t];
        ids[t] = id;
        al[t]  = scoretab[id];
    }
    __syncthreads();
    if (t == 0) {
        float mx = -1e30f;
        for (int w = 0; w < KW; w++) mx = fmaxf(mx, al[w]);
        float sum = 0.f;
        for (int w = 0; w < KW; w++) { float e = __expf(al[w] - mx); al[w] = e; sum += e; }
        sinv = 1.0f / sum;
    }
    __syncthreads();
    if (t < 104) {                       // paired bf16x2 gathers (cols 2t, 2t+1)
        int c = t * 2;
        float a0 = 0.f, a1 = 0.f;
#pragma unroll 5
        for (int w = 0; w < KW; w++) {
            __nv_bfloat162 v = *reinterpret_cast<const __nv_bfloat162*>(
                wencBF + (size_t)ids[w] * KP + c);
            float al_w = al[w];
            a0 += al_w * __bfloat162float(v.x);
            a1 += al_w * __bfloat162float(v.y);
        }
        float inv = sinv;
        __nv_bfloat162 o = __floats2bfloat162_rn(a0 * inv, a1 * inv);
        *reinterpret_cast<__nv_bfloat162*>(svecBF + (size_t)s * KP + c) = o;
    }
}

// ---------------- sentence attention combine: one block per batch row ----
__global__ void sent_attn(const float* __restrict__ scoretab, const float* __restrict__ senc,
                          float* __restrict__ dvec)
{
    int b = blockIdx.x;
    __shared__ float al[KS];
    __shared__ float sinv;
    int t = threadIdx.x;
    if (t < KS) al[t] = scoretab[b * KS + t];
    __syncthreads();
    if (t == 0) {
        float mx = -1e30f;
        for (int i = 0; i < KS; i++) mx = fmaxf(mx, al[i]);
        float sum = 0.f;
        for (int i = 0; i < KS; i++) { float e = __expf(al[i] - mx); al[i] = e; sum += e; }
        sinv = 1.0f / sum;
    }
    __syncthreads();
    if (t < 200) {
        float a = 0.f;
        float inv = sinv;
#pragma unroll 4
        for (int i = 0; i < KS; i++) a += al[i] * senc[(size_t)(b * KS + i) * 200 + t];
        dvec[b * 200 + t] = a * inv;
    }
}

// ---------------- classifier + log_softmax: one warp per batch row -------
__global__ void classifier(const float* __restrict__ dvec, const float* __restrict__ fcW,
                           const float* __restrict__ fcb, float* __restrict__ out)
{
    int b = blockIdx.x;
    int lane = threadIdx.x;
    const float* dv = dvec + b * 200;
    float logit[KNC];
#pragma unroll
    for (int c = 0; c < KNC; c++) {
        float s = 0.f;
        for (int d = lane; d < 200; d += 32) s += dv[d] * fcW[c * 200 + d];
#pragma unroll
        for (int o = 16; o; o >>= 1) s += __shfl_xor_sync(0xffffffffu, s, o);
        logit[c] = s + fcb[c];
    }
    if (lane == 0) {
        float mx = -1e30f;
        for (int c = 0; c < KNC; c++) mx = fmaxf(mx, logit[c]);
        float sum = 0.f;
        for (int c = 0; c < KNC; c++) sum += expf(logit[c] - mx);
        float lse = mx + logf(sum);
        for (int c = 0; c < KNC; c++) out[b * KNC + c] = logit[c] - lse;
    }
}

// ---------------- launch --------------------------------------------------
extern "C" void kernel_launch(void* const* d_in, const int* in_sizes, int n_in,
                              void* d_out, int out_size)
{
    (void)in_sizes; (void)n_in; (void)out_size;
    const int*   x     = (const int*)  d_in[0];
    const float* emb   = (const float*)d_in[1];
    const float* wWihf = (const float*)d_in[2];
    const float* wbihf = (const float*)d_in[3];
    const float* wbhhf = (const float*)d_in[4];
    const float* wWihb = (const float*)d_in[5];
    const float* wbihb = (const float*)d_in[6];
    const float* wbhhb = (const float*)d_in[7];
    const float* waW   = (const float*)d_in[8];
    const float* wab   = (const float*)d_in[9];
    const float* wactx = (const float*)d_in[10];
    const float* sWihf = (const float*)d_in[11];
    const float* sbihf = (const float*)d_in[12];
    const float* sbhhf = (const float*)d_in[13];
    const float* sWihb = (const float*)d_in[14];
    const float* sbihb = (const float*)d_in[15];
    const float* sbhhb = (const float*)d_in[16];
    const float* saW   = (const float*)d_in[17];
    const float* sab   = (const float*)d_in[18];
    const float* sactx = (const float*)d_in[19];
    const float* fcW   = (const float*)d_in[20];
    const float* fcb   = (const float*)d_in[21];
    float* out = (float*)d_out;

    __nv_bfloat16 *embBF, *wencBF, *svecBF, *sencBF, *WgruW, *WgruS, *WattnW, *WattnS;
    float *scorew, *sencF, *scores, *dvec;
    cudaGetSymbolAddress((void**)&embBF,  g_embBF);
    cudaGetSymbolAddress((void**)&wencBF, g_wencBF);
    cudaGetSymbolAddress((void**)&scorew, g_scorew);
    cudaGetSymbolAddress((void**)&svecBF, g_svecBF);
    cudaGetSymbolAddress((void**)&sencF,  g_sencF);
    cudaGetSymbolAddress((void**)&sencBF, g_sencBF);
    cudaGetSymbolAddress((void**)&scores, g_scores);
    cudaGetSymbolAddress((void**)&dvec,   g_dvec);
    cudaGetSymbolAddress((void**)&WgruW,  g_WgruW);
    cudaGetSymbolAddress((void**)&WgruS,  g_WgruS);
    cudaGetSymbolAddress((void**)&WattnW, g_WattnW);
    cudaGetSymbolAddress((void**)&WattnS, g_WattnS);

    const int GRU_SMEM = 64 * SGS * 4;   // 157696 B (loop staging 43008 B aliases)
    cudaFuncSetAttribute(fused_gru_gemm, cudaFuncAttributeMaxDynamicSharedMemorySize, GRU_SMEM);

    // prep: bf16 conversions with K/N padding
    conv_pad<<<(KVOCAB * KP + 255) / 256, 256>>>(emb, embBF, KVOCAB);
    prep_gruW<<<(NG * KP + 255) / 256, 256>>>(wWihf, wWihb, WgruW);
    prep_gruW<<<(NG * KP + 255) / 256, 256>>>(sWihf, sWihb, WgruS);
    prep_attnW<<<(NA * KP + 255) / 256, 256>>>(waW, WattnW);
    prep_attnW<<<(NA * KP + 255) / 256, 256>>>(saW, WattnS);

    // word stage (per-vocab tables)
    fused_gru_gemm<<<(KVOCAB + 63) / 64, 256, GRU_SMEM>>>(
        embBF, WgruW, wbihf, wbhhf, wbihb, wbhhb, nullptr, wencBF, KVOCAB);
    fused_score<<<(KVOCAB + 63) / 64, 256>>>(wencBF, WattnW, wab, wactx, scorew, KVOCAB);
    word_attn<<<KSENT, 128>>>(x, scorew, wencBF, svecBF);

    // sentence stage
    fused_gru_gemm<<<(KSENT + 63) / 64, 256, GRU_SMEM>>>(
        svecBF, WgruS, sbihf, sbhhf, sbihb, sbhhb, sencF, sencBF, KSENT);
    fused_score<<<(KSENT + 63) / 64, 256>>>(sencBF, WattnS, sab, sactx, scores, KSENT);
    sent_attn<<<KB, 256>>>(scores, sencF, dvec);
    classifier<<<KB, 32>>>(dvec, fcW, fcb, out);
}

// round 9
// speedup vs baseline: 3.5556x; 1.1168x over previous
#include <cuda_runtime.h>
#include <cuda_bf16.h>
#include <cstddef>
#include <cstdint>

// ---------------- problem constants ----------------
#define KVOCAB 100000
#define KED    200
#define KH     100      // HW == HS == 100
#define KNC    10
#define KB     128
#define KS     40
#define KW     50
#define KSENT  (KB * KS)          // 5120

#define KP     208      // K padded (13 * 16)
#define NG     608      // GRU gate width padded (600 -> 608)
#define NA     224      // attention proj width padded (200 -> 224)
#define SGS    616      // bf16 staging stride (608+8)
#define TRS    48       // smem tile row stride in BYTES (16 bf16 data + 16B pad: conflict-free LDSM)

// ---------------- scratch (__device__ globals; no allocations allowed) ----
__device__ __nv_bfloat16 g_embBF[(size_t)KVOCAB * KP];   // 41.6 MB
__device__ __nv_bfloat16 g_wencBF[(size_t)KVOCAB * KP];  // 41.6 MB
__device__ float         g_scorew[KVOCAB];
__device__ __nv_bfloat16 g_svecBF[KSENT * KP];
__device__ float         g_sencF[KSENT * 200];
__device__ __nv_bfloat16 g_sencBF[KSENT * KP];
__device__ float         g_scores[KSENT];
__device__ float         g_dvec[KB * 200];
__device__ __nv_bfloat16 g_WgruW[NG * KP];
__device__ __nv_bfloat16 g_WgruS[NG * KP];
__device__ __nv_bfloat16 g_WattnW[NA * KP];
__device__ __nv_bfloat16 g_WattnS[NA * KP];

// ---------------- math / ptx helpers --------------------------------------
__device__ __forceinline__ float fast_tanh(float x) {
    float y; asm("tanh.approx.f32 %0, %1;" : "=f"(y) : "f"(x)); return y;
}
__device__ __forceinline__ float sigmf(float x) {
    return 0.5f * fast_tanh(0.5f * x) + 0.5f;
}
__device__ __forceinline__ void mma_bf16(float c[4],
    uint32_t a0, uint32_t a1, uint32_t a2, uint32_t a3, uint32_t b0, uint32_t b1)
{
    asm volatile(
        "mma.sync.aligned.m16n8k16.row.col.f32.bf16.bf16.f32 "
        "{%0,%1,%2,%3}, {%4,%5,%6,%7}, {%8,%9}, {%0,%1,%2,%3};"
        : "+f"(c[0]), "+f"(c[1]), "+f"(c[2]), "+f"(c[3])
        : "r"(a0), "r"(a1), "r"(a2), "r"(a3), "r"(b0), "r"(b1));
}
__device__ __forceinline__ void ldsm4(uint32_t& r0, uint32_t& r1, uint32_t& r2, uint32_t& r3,
                                      uint32_t addr)
{
    asm volatile("ldmatrix.sync.aligned.m8n8.x4.shared.b16 {%0,%1,%2,%3}, [%4];"
                 : "=r"(r0), "=r"(r1), "=r"(r2), "=r"(r3) : "r"(addr));
}
__device__ __forceinline__ void ldsm2(uint32_t& r0, uint32_t& r1, uint32_t addr)
{
    asm volatile("ldmatrix.sync.aligned.m8n8.x2.shared.b16 {%0,%1}, [%2];"
                 : "=r"(r0), "=r"(r1) : "r"(addr));
}
__device__ __forceinline__ void cp16(void* dst_smem, const void* src, bool ok) {
    uint32_t d = (uint32_t)__cvta_generic_to_shared(dst_smem);
    int sz = ok ? 16 : 0;
    asm volatile("cp.async.cg.shared.global [%0], [%1], 16, %2;"
                 :: "r"(d), "l"(src), "r"(sz) : "memory");
}
__device__ __forceinline__ void cp_commit() {
    asm volatile("cp.async.commit_group;" ::: "memory");
}
template <int N>
__device__ __forceinline__ void cp_wait() {
    asm volatile("cp.async.wait_group %0;" :: "n"(N) : "memory");
}
__device__ __forceinline__ uint32_t bf2pack(float lo, float hi) {
    __nv_bfloat162 v = __floats2bfloat162_rn(lo, hi);
    return *reinterpret_cast<uint32_t*>(&v);
}

// ---------------- prep kernels -------------------------------------------
// fp32 [M][200] -> bf16 [M][208], vectorized (4 cols/thread)
__global__ void conv_pad(const float* __restrict__ src, __nv_bfloat16* __restrict__ dst, int M)
{
    int i = blockIdx.x * blockDim.x + threadIdx.x;
    if (i >= M * 52) return;
    int m = i / 52, c4 = i - m * 52;
    float4 v = make_float4(0.f, 0.f, 0.f, 0.f);
    if (c4 < 50) v = *reinterpret_cast<const float4*>(src + (size_t)m * 200 + c4 * 4);
    uint2 o;
    o.x = bf2pack(v.x, v.y);
    o.y = bf2pack(v.z, v.w);
    *reinterpret_cast<uint2*>(dst + (size_t)m * KP + c4 * 4) = o;
}
__global__ void prep_gruW(const float* __restrict__ wf, const float* __restrict__ wb,
                          __nv_bfloat16* __restrict__ dst)
{
    int i = blockIdx.x * blockDim.x + threadIdx.x;
    if (i >= NG * KP) return;
    int r = i / KP, c = i - r * KP;
    float v = 0.f;
    if (c < 200) {
        if (r < 300)      v = wf[r * 200 + c];
        else if (r < 600) v = wb[(r - 300) * 200 + c];
    }
    dst[i] = __float2bfloat16(v);
}
// both attention weights in one launch (keeps fused_gru_gemm in profiled slot #5)
__global__ void prep_attnW2(const float* __restrict__ w0, const float* __restrict__ w1,
                            __nv_bfloat16* __restrict__ d0, __nv_bfloat16* __restrict__ d1)
{
    int i = blockIdx.x * blockDim.x + threadIdx.x;
    if (i >= 2 * NA * KP) return;
    const float* w = (i < NA * KP) ? w0 : w1;
    __nv_bfloat16* d = (i < NA * KP) ? d0 : d1;
    int j = (i < NA * KP) ? i : i - NA * KP;
    int r = j / KP, c = j - r * KP;
    float v = (r < 200 && c < 200) ? w[r * 200 + c] : 0.f;
    d[j] = __float2bfloat16(v);
}

// ---------------- fused GEMM(bf16 mma, ldmatrix, pipelined) + GRU ---------
// 512 thr (16 warps: 4M x 4N). M-tile 64 (16 rows/warp), N=608, K=208.
// cp.async double-buffered, 48B-row tiles (conflict-free LDSM), bf16 gate staging.
__global__ __launch_bounds__(512, 1)
void fused_gru_gemm(const __nv_bfloat16* __restrict__ A, const __nv_bfloat16* __restrict__ W,
                    const float* __restrict__ bihf, const float* __restrict__ bhhf,
                    const float* __restrict__ bihb, const float* __restrict__ bhhb,
                    float* __restrict__ hF, __nv_bfloat16* __restrict__ hBF, int M)
{
    extern __shared__ __align__(16) char smraw[];
    // loop tiles: B 2*NG*48 B, then A 2*64*48 B (aliased by bf16 staging Sg)
    __nv_bfloat16* Sg = (__nv_bfloat16*)smraw;

    const int tid = threadIdx.x, wid = tid >> 5, lane = tid & 31;
    const int gq = lane >> 2, qp = lane & 3;
    const int mW = wid >> 2, nW = wid & 3;           // mW 0..3 (16 rows), nW 0..3 (152 cols)
    const int mBase = blockIdx.x * 64;

    const uint32_t sbase = (uint32_t)__cvta_generic_to_shared(smraw);
    const uint32_t AsBase = sbase + 2 * NG * TRS;
    const int l15 = lane & 15, lHi = (lane >> 4) << 4;

    const uint32_t aOff = (uint32_t)((mW * 16 + l15) * TRS + lHi);
    uint32_t bOff[9];
#pragma unroll
    for (int p = 0; p < 9; p++)
        bOff[p] = (uint32_t)((nW * 152 + p * 16 + l15) * TRS + lHi);
    const uint32_t bOffL = (uint32_t)((nW * 152 + 144 + (lane & 7)) * TRS + (((lane >> 3) & 1) << 4));

    float acc[19][4];
#pragma unroll
    for (int t = 0; t < 19; t++)
#pragma unroll
        for (int q = 0; q < 4; q++) acc[t][q] = 0.f;

    auto loadTiles = [&](int kt, int buf) {
        const int k0 = kt * 16;
        char* Bd = smraw + buf * NG * TRS;
        char* Ad = smraw + 2 * NG * TRS + buf * 64 * TRS;
        for (int c = tid; c < NG * 2; c += 512) {
            int n = c >> 1, h = c & 1;
            cp16(Bd + n * TRS + h * 16, W + (size_t)n * KP + k0 + h * 8, true);
        }
        if (tid < 128) {
            int r = tid >> 1, h = tid & 1;
            int gm = mBase + r;
            bool ok = gm < M;
            cp16(Ad + r * TRS + h * 16, A + (size_t)(ok ? gm : 0) * KP + k0 + h * 8, ok);
        }
    };

    loadTiles(0, 0);
    cp_commit();

    for (int kt = 0; kt < 13; kt++) {
        const int buf = kt & 1;
        if (kt + 1 < 13) { loadTiles(kt + 1, buf ^ 1); cp_commit(); cp_wait<1>(); }
        else             { cp_wait<0>(); }
        __syncthreads();

        const uint32_t AsB = AsBase + buf * 64 * TRS;
        const uint32_t BsB = sbase + buf * NG * TRS;
        uint32_t a0, a1, a2, a3;
        ldsm4(a0, a1, a2, a3, AsB + aOff);
#pragma unroll
        for (int p = 0; p < 9; p++) {
            uint32_t b00, b10, b01, b11;   // tile0.b0, tile1.b0, tile0.b1, tile1.b1
            ldsm4(b00, b10, b01, b11, BsB + bOff[p]);
            mma_bf16(acc[2 * p],     a0, a1, a2, a3, b00, b01);
            mma_bf16(acc[2 * p + 1], a0, a1, a2, a3, b10, b11);
        }
        {
            uint32_t bl0, bl1;
            ldsm2(bl0, bl1, BsB + bOffL);
            mma_bf16(acc[18], a0, a1, a2, a3, bl0, bl1);
        }
        __syncthreads();
    }

    // stage gate tile as bf16 (stride 616)
#pragma unroll
    for (int t = 0; t < 19; t++) {
        int r = mW * 16 + gq, c = nW * 152 + t * 8 + qp * 2;
        *reinterpret_cast<uint32_t*>(&Sg[r * SGS + c])       = bf2pack(acc[t][0], acc[t][1]);
        *reinterpret_cast<uint32_t*>(&Sg[(r + 8) * SGS + c]) = bf2pack(acc[t][2], acc[t][3]);
    }
    __syncthreads();

    // GRU pointwise from bf16-staged gates
    for (int i = tid; i < 64 * KH; i += 512) {
        int m = i / KH, d = i - m * KH;
        int gm = mBase + m;
        if (gm >= M) continue;
        const __nv_bfloat16* row = Sg + m * SGS;
        float rf = sigmf(__bfloat162float(row[d])       + __ldg(bihf + d)       + __ldg(bhhf + d));
        float zf = sigmf(__bfloat162float(row[100 + d]) + __ldg(bihf + 100 + d) + __ldg(bhhf + 100 + d));
        float nf = fast_tanh(__bfloat162float(row[200 + d]) + __ldg(bihf + 200 + d) + rf * __ldg(bhhf + 200 + d));
        float hf = (1.f - zf) * nf;
        float rb = sigmf(__bfloat162float(row[300 + d]) + __ldg(bihb + d)       + __ldg(bhhb + d));
        float zb = sigmf(__bfloat162float(row[400 + d]) + __ldg(bihb + 100 + d) + __ldg(bhhb + 100 + d));
        float nb = fast_tanh(__bfloat162float(row[500 + d]) + __ldg(bihb + 200 + d) + rb * __ldg(bhhb + 200 + d));
        float hb = (1.f - zb) * nb;
        if (hF) { hF[(size_t)gm * 200 + d] = hf; hF[(size_t)gm * 200 + 100 + d] = hb; }
        hBF[(size_t)gm * KP + d]       = __float2bfloat16(hf);
        hBF[(size_t)gm * KP + 100 + d] = __float2bfloat16(hb);
    }
    for (int j = tid; j < 64 * 8; j += 512) {   // zero the K-pad columns
        int m = j >> 3, gm = mBase + m;
        if (gm < M) hBF[(size_t)gm * KP + 200 + (j & 7)] = __float2bfloat16(0.f);
    }
}

// ---------------- fused GEMM(bf16 mma, ldmatrix) + ctx . tanh(U + b) -----
// 256 thr (8 warps: 2M x 4N). M-tile 64 (32 rows/warp), N=224, K=208.
__global__ __launch_bounds__(256, 1)
void fused_score(const __nv_bfloat16* __restrict__ A, const __nv_bfloat16* __restrict__ W,
                 const float* __restrict__ bias, const float* __restrict__ ctx,
                 float* __restrict__ score, int M)
{
    __shared__ __align__(16) char BsRaw[2 * NA * TRS];
    __shared__ __align__(16) char AsRaw[2 * 64 * TRS];
    __shared__ float ctxs[NA], biass[NA], part[64];

    const int tid = threadIdx.x, wid = tid >> 5, lane = tid & 31;
    const int gq = lane >> 2, qp = lane & 3;
    const int mW = wid >> 2, nW = wid & 3;          // mW 0..1 (32 rows), nW 0..3 (56 cols)
    const int mBase = blockIdx.x * 64;

    const uint32_t BsBase = (uint32_t)__cvta_generic_to_shared(BsRaw);
    const uint32_t AsBase = (uint32_t)__cvta_generic_to_shared(AsRaw);
    const int l15 = lane & 15, lHi = (lane >> 4) << 4;

    uint32_t aOff[2];
#pragma unroll
    for (int mi = 0; mi < 2; mi++)
        aOff[mi] = (uint32_t)((mW * 32 + mi * 16 + l15) * TRS + lHi);
    uint32_t bOff[3];
#pragma unroll
    for (int p = 0; p < 3; p++)
        bOff[p] = (uint32_t)((nW * 56 + p * 16 + l15) * TRS + lHi);
    const uint32_t bOffL = (uint32_t)((nW * 56 + 48 + (lane & 7)) * TRS + (((lane >> 3) & 1) << 4));

    if (tid < NA) {
        ctxs[tid]  = (tid < 200) ? ctx[tid]  : 0.f;
        biass[tid] = (tid < 200) ? bias[tid] : 0.f;
    }
    if (tid < 64) part[tid] = 0.f;

    float acc[2][7][4];
#pragma unroll
    for (int mi = 0; mi < 2; mi++)
#pragma unroll
        for (int t = 0; t < 7; t++)
#pragma unroll
            for (int q = 0; q < 4; q++) acc[mi][t][q] = 0.f;

    auto loadTiles = [&](int kt, int buf) {
        const int k0 = kt * 16;
        char* Bd = BsRaw + buf * NA * TRS;
        char* Ad = AsRaw + buf * 64 * TRS;
        for (int c = tid; c < NA * 2; c += 256) {
            int n = c >> 1, h = c & 1;
            cp16(Bd + n * TRS + h * 16, W + (size_t)n * KP + k0 + h * 8, true);
        }
        if (tid < 128) {
            int r = tid >> 1, h = tid & 1;
            int gm = mBase + r;
            bool ok = gm < M;
            cp16(Ad + r * TRS + h * 16, A + (size_t)(ok ? gm : 0) * KP + k0 + h * 8, ok);
        }
    };

    loadTiles(0, 0);
    cp_commit();

    for (int kt = 0; kt < 13; kt++) {
        const int buf = kt & 1;
        if (kt + 1 < 13) { loadTiles(kt + 1, buf ^ 1); cp_commit(); cp_wait<1>(); }
        else             { cp_wait<0>(); }
        __syncthreads();

        const uint32_t AsB = AsBase + buf * 64 * TRS;
        const uint32_t BsB = BsBase + buf * NA * TRS;
        uint32_t a[2][4];
#pragma unroll
        for (int mi = 0; mi < 2; mi++)
            ldsm4(a[mi][0], a[mi][1], a[mi][2], a[mi][3], AsB + aOff[mi]);
#pragma unroll
        for (int p = 0; p < 3; p++) {
            uint32_t b00, b10, b01, b11;
            ldsm4(b00, b10, b01, b11, BsB + bOff[p]);
#pragma unroll
            for (int mi = 0; mi < 2; mi++) {
                mma_bf16(acc[mi][2 * p],     a[mi][0], a[mi][1], a[mi][2], a[mi][3], b00, b01);
                mma_bf16(acc[mi][2 * p + 1], a[mi][0], a[mi][1], a[mi][2], a[mi][3], b10, b11);
            }
        }
        {
            uint32_t bl0, bl1;
            ldsm2(bl0, bl1, BsB + bOffL);
#pragma unroll
            for (int mi = 0; mi < 2; mi++)
                mma_bf16(acc[mi][6], a[mi][0], a[mi][1], a[mi][2], a[mi][3], bl0, bl1);
        }
        __syncthreads();
    }

#pragma unroll
    for (int mi = 0; mi < 2; mi++) {
        float s0 = 0.f, s1 = 0.f;
#pragma unroll
        for (int t = 0; t < 7; t++) {
            int c0 = nW * 56 + t * 8 + qp * 2;
            s0 += ctxs[c0]     * fast_tanh(acc[mi][t][0] + biass[c0]);
            s0 += ctxs[c0 + 1] * fast_tanh(acc[mi][t][1] + biass[c0 + 1]);
            s1 += ctxs[c0]     * fast_tanh(acc[mi][t][2] + biass[c0]);
            s1 += ctxs[c0 + 1] * fast_tanh(acc[mi][t][3] + biass[c0 + 1]);
        }
        atomicAdd(&part[mW * 32 + mi * 16 + gq],     s0);
        atomicAdd(&part[mW * 32 + mi * 16 + gq + 8], s1);
    }
    __syncthreads();
    if (tid < 64 && mBase + tid < M) score[mBase + tid] = part[tid];
}

// ---------------- word attention combine: one block per sentence ---------
__global__ void word_attn(const int* __restrict__ x, const float* __restrict__ scoretab,
                          const __nv_bfloat16* __restrict__ wencBF,
                          __nv_bfloat16* __restrict__ svecBF)
{
    int s = blockIdx.x;
    __shared__ int   ids[KW];
    __shared__ float al[KW];
    __shared__ float sinv;
    int t = threadIdx.x;                 // 128 threads
    if (t < KW) {
        int id = x[s * KW + t];
        ids[t] = id;
        al[t]  = scoretab[id];
    }
    __syncthreads();
    if (t == 0) {
        float mx = -1e30f;
        for (int w = 0; w < KW; w++) mx = fmaxf(mx, al[w]);
        float sum = 0.f;
        for (int w = 0; w < KW; w++) { float e = __expf(al[w] - mx); al[w] = e; sum += e; }
        sinv = 1.0f / sum;
    }
    __syncthreads();
    if (t < 104) {                       // paired bf16x2 gathers (cols 2t, 2t+1)
        int c = t * 2;
        float a0 = 0.f, a1 = 0.f;
#pragma unroll 5
        for (int w = 0; w < KW; w++) {
            __nv_bfloat162 v = *reinterpret_cast<const __nv_bfloat162*>(
                wencBF + (size_t)ids[w] * KP + c);
            float al_w = al[w];
            a0 += al_w * __bfloat162float(v.x);
            a1 += al_w * __bfloat162float(v.y);
        }
        float inv = sinv;
        __nv_bfloat162 o = __floats2bfloat162_rn(a0 * inv, a1 * inv);
        *reinterpret_cast<__nv_bfloat162*>(svecBF + (size_t)s * KP + c) = o;
    }
}

// ---------------- sentence attention combine: one block per batch row ----
__global__ void sent_attn(const float* __restrict__ scoretab, const float* __restrict__ senc,
                          float* __restrict__ dvec)
{
    int b = blockIdx.x;
    __shared__ float al[KS];
    __shared__ float sinv;
    int t = threadIdx.x;
    if (t < KS) al[t] = scoretab[b * KS + t];
    __syncthreads();
    if (t == 0) {
        float mx = -1e30f;
        for (int i = 0; i < KS; i++) mx = fmaxf(mx, al[i]);
        float sum = 0.f;
        for (int i = 0; i < KS; i++) { float e = __expf(al[i] - mx); al[i] = e; sum += e; }
        sinv = 1.0f / sum;
    }
    __syncthreads();
    if (t < 200) {
        float a = 0.f;
        float inv = sinv;
#pragma unroll 4
        for (int i = 0; i < KS; i++) a += al[i] * senc[(size_t)(b * KS + i) * 200 + t];
        dvec[b * 200 + t] = a * inv;
    }
}

// ---------------- classifier + log_softmax: one warp per batch row -------
__global__ void classifier(const float* __restrict__ dvec, const float* __restrict__ fcW,
                           const float* __restrict__ fcb, float* __restrict__ out)
{
    int b = blockIdx.x;
    int lane = threadIdx.x;
    const float* dv = dvec + b * 200;
    float logit[KNC];
#pragma unroll
    for (int c = 0; c < KNC; c++) {
        float s = 0.f;
        for (int d = lane; d < 200; d += 32) s += dv[d] * fcW[c * 200 + d];
#pragma unroll
        for (int o = 16; o; o >>= 1) s += __shfl_xor_sync(0xffffffffu, s, o);
        logit[c] = s + fcb[c];
    }
    if (lane == 0) {
        float mx = -1e30f;
        for (int c = 0; c < KNC; c++) mx = fmaxf(mx, logit[c]);
        float sum = 0.f;
        for (int c = 0; c < KNC; c++) sum += expf(logit[c] - mx);
        float lse = mx + logf(sum);
        for (int c = 0; c < KNC; c++) out[b * KNC + c] = logit[c] - lse;
    }
}

// ---------------- launch --------------------------------------------------
extern "C" void kernel_launch(void* const* d_in, const int* in_sizes, int n_in,
                              void* d_out, int out_size)
{
    (void)in_sizes; (void)n_in; (void)out_size;
    const int*   x     = (const int*)  d_in[0];
    const float* emb   = (const float*)d_in[1];
    const float* wWihf = (const float*)d_in[2];
    const float* wbihf = (const float*)d_in[3];
    const float* wbhhf = (const float*)d_in[4];
    const float* wWihb = (const float*)d_in[5];
    const float* wbihb = (const float*)d_in[6];
    const float* wbhhb = (const float*)d_in[7];
    const float* waW   = (const float*)d_in[8];
    const float* wab   = (const float*)d_in[9];
    const float* wactx = (const float*)d_in[10];
    const float* sWihf = (const float*)d_in[11];
    const float* sbihf = (const float*)d_in[12];
    const float* sbhhf = (const float*)d_in[13];
    const float* sWihb = (const float*)d_in[14];
    const float* sbihb = (const float*)d_in[15];
    const float* sbhhb = (const float*)d_in[16];
    const float* saW   = (const float*)d_in[17];
    const float* sab   = (const float*)d_in[18];
    const float* sactx = (const float*)d_in[19];
    const float* fcW   = (const float*)d_in[20];
    const float* fcb   = (const float*)d_in[21];
    float* out = (float*)d_out;

    __nv_bfloat16 *embBF, *wencBF, *svecBF, *sencBF, *WgruW, *WgruS, *WattnW, *WattnS;
    float *scorew, *sencF, *scores, *dvec;
    cudaGetSymbolAddress((void**)&embBF,  g_embBF);
    cudaGetSymbolAddress((void**)&wencBF, g_wencBF);
    cudaGetSymbolAddress((void**)&scorew, g_scorew);
    cudaGetSymbolAddress((void**)&svecBF, g_svecBF);
    cudaGetSymbolAddress((void**)&sencF,  g_sencF);
    cudaGetSymbolAddress((void**)&sencBF, g_sencBF);
    cudaGetSymbolAddress((void**)&scores, g_scores);
    cudaGetSymbolAddress((void**)&dvec,   g_dvec);
    cudaGetSymbolAddress((void**)&WgruW,  g_WgruW);
    cudaGetSymbolAddress((void**)&WgruS,  g_WgruS);
    cudaGetSymbolAddress((void**)&WattnW, g_WattnW);
    cudaGetSymbolAddress((void**)&WattnS, g_WattnS);

    // dyn smem = max(bf16 staging 64*616*2, loop tiles 2*(608+64)*48) = 78848 B
    const int GRU_SMEM = 64 * SGS * 2;
    cudaFuncSetAttribute(fused_gru_gemm, cudaFuncAttributeMaxDynamicSharedMemorySize, GRU_SMEM);

    // prep (4 launches so fused_gru_gemm is launch #5 for the ncu capture slot)
    conv_pad<<<(KVOCAB * 52 + 255) / 256, 256>>>(emb, embBF, KVOCAB);
    prep_gruW<<<(NG * KP + 255) / 256, 256>>>(wWihf, wWihb, WgruW);
    prep_gruW<<<(NG * KP + 255) / 256, 256>>>(sWihf, sWihb, WgruS);
    prep_attnW2<<<(2 * NA * KP + 255) / 256, 256>>>(waW, saW, WattnW, WattnS);

    // word stage (per-vocab tables)
    fused_gru_gemm<<<(KVOCAB + 63) / 64, 512, GRU_SMEM>>>(
        embBF, WgruW, wbihf, wbhhf, wbihb, wbhhb, nullptr, wencBF, KVOCAB);
    fused_score<<<(KVOCAB + 63) / 64, 256>>>(wencBF, WattnW, wab, wactx, scorew, KVOCAB);
    word_attn<<<KSENT, 128>>>(x, scorew, wencBF, svecBF);

    // sentence stage
    fused_gru_gemm<<<(KSENT + 63) / 64, 512, GRU_SMEM>>>(
        svecBF, WgruS, sbihf, sbhhf, sbihb, sbhhb, sencF, sencBF, KSENT);
    fused_score<<<(KSENT + 63) / 64, 256>>>(sencBF, WattnS, sab, sactx, scores, KSENT);
    sent_attn<<<KB, 256>>>(scores, sencF, dvec);
    classifier<<<KB, 32>>>(dvec, fcW, fcb, out);
}